// round 11
// baseline (speedup 1.0000x reference)
#include <cuda_runtime.h>
#include <cuda_bf16.h>
#include <math.h>
#include <stdint.h>

// Problem constants
#define BB   2
#define LL   2048
#define DD   2048
#define HH   16
#define KVH  4
#define EE   128
#define ML   (BB*LL)        // 4096 rows total
#define HE   (HH*EE)        // 2048
#define KVE  (KVH*EE)       // 512
#define QKVN 3072           // fused Q|K|V projection width

// -------- scratch (device globals; no allocation allowed) --------
__device__ __nv_bfloat16 g_xb[ML*DD];         // x in bf16
__device__ __nv_bfloat16 g_Wqkvt[QKVN*DD];    // [Wq|Wk|Wv]^T [N=3072][K=2048] bf16
__device__ __nv_bfloat16 g_Wot[DD*HE];        // Wo^T [N=2048][K=2048] bf16
__device__ float         g_bqkv[QKVN];        // bq|bk|bv
__device__ __nv_bfloat16 g_QKV[ML*QKVN];      // fused QKV output, row stride 3072
__device__ __nv_bfloat16 g_CTXb[ML*HE];       // attention output bf16
__device__ float         g_Y[ML*DD];          // pre-GELU O-proj output fp32

// ---------------- helpers ----------------
__device__ __forceinline__ void mma16(float* d, const unsigned* a, const unsigned* b) {
    asm volatile(
        "mma.sync.aligned.m16n8k16.row.col.f32.bf16.bf16.f32 "
        "{%0,%1,%2,%3}, {%4,%5,%6,%7}, {%8,%9}, {%0,%1,%2,%3};\n"
        : "+f"(d[0]), "+f"(d[1]), "+f"(d[2]), "+f"(d[3])
        : "r"(a[0]), "r"(a[1]), "r"(a[2]), "r"(a[3]),
          "r"(b[0]), "r"(b[1]));
}

__device__ __forceinline__ void ldsm4(unsigned* r, unsigned addr) {
    asm volatile("ldmatrix.sync.aligned.m8n8.x4.shared.b16 {%0,%1,%2,%3}, [%4];"
                 : "=r"(r[0]), "=r"(r[1]), "=r"(r[2]), "=r"(r[3]) : "r"(addr));
}

__device__ __forceinline__ void ldsm4t(unsigned* r, unsigned addr) {
    asm volatile("ldmatrix.sync.aligned.m8n8.x4.trans.shared.b16 {%0,%1,%2,%3}, [%4];"
                 : "=r"(r[0]), "=r"(r[1]), "=r"(r[2]), "=r"(r[3]) : "r"(addr));
}

__device__ __forceinline__ void cp16(unsigned smem_dst, const void* gmem_src) {
    asm volatile("cp.async.cg.shared.global [%0], [%1], 16;\n" :: "r"(smem_dst), "l"(gmem_src));
}

__device__ __forceinline__ unsigned bf2pack(float x, float y) {
    __nv_bfloat162 v = __float22bfloat162_rn(make_float2(x, y));
    return *(unsigned*)&v;
}

__device__ __forceinline__ unsigned smem_u32(const void* p) {
    unsigned a;
    asm("{ .reg .u64 t; cvta.to.shared.u64 t, %1; cvt.u32.u64 %0, t; }" : "=r"(a) : "l"(p));
    return a;
}

// ============================================================
// Fused prep kernel (single launch)
// ============================================================
#define PREP_BLOCKS 18444

__device__ __forceinline__ void transp_tile(float (*t)[33],
                                            const float* __restrict__ W,
                                            __nv_bfloat16* __restrict__ Wt,
                                            int Kd, int Nd, int bx, int by, int tid)
{
    const int n0 = bx * 32, k0 = by * 32;
    const int tx = tid & 31, ty = tid >> 5;
    #pragma unroll
    for (int i = 0; i < 4; i++)
        t[ty + 8*i][tx] = W[(size_t)(k0 + ty + 8*i) * Nd + n0 + tx];
    __syncthreads();
    #pragma unroll
    for (int i = 0; i < 4; i++)
        Wt[(size_t)(n0 + ty + 8*i) * Kd + k0 + tx] = __float2bfloat16(t[tx][ty + 8*i]);
}

__global__ __launch_bounds__(256)
void prep_all(const float* __restrict__ x,
              const float* __restrict__ Wq, const float* __restrict__ Wk,
              const float* __restrict__ Wv, const float* __restrict__ Wo,
              const float* __restrict__ bq, const float* __restrict__ bk,
              const float* __restrict__ bv,
              __nv_bfloat16* __restrict__ xb, __nv_bfloat16* __restrict__ Wqkvt,
              __nv_bfloat16* __restrict__ Wot, float* __restrict__ bqkv)
{
    __shared__ float t[32][33];
    const int bid = blockIdx.x;
    const int tid = threadIdx.x;

    if (bid < 8192) {
        int i = bid * 256 + tid;
        float4 v = ((const float4*)x)[i];
        uint2 o;
        o.x = bf2pack(v.x, v.y);
        o.y = bf2pack(v.z, v.w);
        ((uint2*)xb)[i] = o;
    } else if (bid < 12288) {
        int tt = bid - 8192;
        transp_tile(t, Wq, Wqkvt, DD, HE, tt & 63, tt >> 6, tid);
    } else if (bid < 13312) {
        int tt = bid - 12288;
        transp_tile(t, Wk, Wqkvt + (size_t)2048*DD, DD, KVE, tt & 15, tt >> 4, tid);
    } else if (bid < 14336) {
        int tt = bid - 13312;
        transp_tile(t, Wv, Wqkvt + (size_t)2560*DD, DD, KVE, tt & 15, tt >> 4, tid);
    } else if (bid < 18432) {
        int tt = bid - 14336;
        transp_tile(t, Wo, Wot, HE, DD, tt & 63, tt >> 6, tid);
    } else {
        int i = (bid - 18432) * 256 + tid;
        if (i < 2048)        bqkv[i] = bq[i];
        else if (i < 2560)   bqkv[i] = bk[i - 2048];
        else if (i < 3072)   bqkv[i] = bv[i - 2560];
    }
}

// ============================================================
// bf16 tensor-core GEMM (mma.sync + ldmatrix), 4-stage cp.async pipeline.
// C[M,N] = A[M,K] @ W[K,N] + bias[N];  Bt = W^T [N][K] bf16.
// CTA tile 256x128, BK=32, 512 threads = 16 warps (64x32 warp tile, 4x4).
// ============================================================
#define GBK    32
#define GPAD   40                        // halves/row (80B, LDSM conflict-free)
#define A_ST   (256*GPAD*2)              // 20480 B per A stage
#define B_ST   (128*GPAD*2)              // 10240 B per B stage
#define GSTG   4
#define GEMM_SMEM (GSTG*(A_ST + B_ST))   // 122880 B

template<bool OUT_BF16>
__global__ __launch_bounds__(512)
void gemm_bf16(const __nv_bfloat16* __restrict__ A, const __nv_bfloat16* __restrict__ Bt,
               const float* __restrict__ bias, void* __restrict__ Cout,
               int M, int N, int K, int ldc)
{
    extern __shared__ __nv_bfloat16 gsm[];
    const unsigned AsU = smem_u32(gsm);
    const unsigned BsU = AsU + GSTG * A_ST;

    const int tid  = threadIdx.x;
    const int w    = tid >> 5, lane = tid & 31;
    const int lt   = lane & 3;
    const int l7   = lane & 7, g = lane >> 3;
    const int wm   = w & 3, wn = w >> 2;        // 4x4 warp grid
    const int bx   = blockIdx.x, by = blockIdx.y;

    const __nv_bfloat16* Ag = A  + (size_t)(by * 256) * K;
    const __nv_bfloat16* Bg = Bt + (size_t)(bx * 128) * K;

    float acc[4][4][4];
    #pragma unroll
    for (int mt = 0; mt < 4; mt++)
        #pragma unroll
        for (int nt = 0; nt < 4; nt++)
            #pragma unroll
            for (int f = 0; f < 4; f++) acc[mt][nt][f] = 0.f;

    const int KT = K / GBK;

    auto issue = [&](int kt) {
        if (kt < KT) {
            const int buf = kt & (GSTG - 1);
            const int k0 = kt * GBK;
            // A: 256 rows x 4 chunks = 1024; 2 per thread
            #pragma unroll
            for (int i = 0; i < 2; i++) {
                int q = tid + i * 512;
                int r = q >> 2, c8 = (q & 3) * 8;
                cp16(AsU + buf*A_ST + (r*GPAD + c8)*2, Ag + (size_t)r * K + k0 + c8);
            }
            // B: 128 rows x 4 chunks = 512; 1 per thread
            {
                int r = tid >> 2, c8 = (tid & 3) * 8;
                cp16(BsU + buf*B_ST + (r*GPAD + c8)*2, Bg + (size_t)r * K + k0 + c8);
            }
        }
        asm volatile("cp.async.commit_group;\n");   // empty group past the end
    };

    issue(0); issue(1); issue(2);

    for (int kt = 0; kt < KT; ++kt) {
        asm volatile("cp.async.wait_group 2;\n");   // group kt complete
        __syncthreads();
        issue(kt + 3);

        const int buf = kt & (GSTG - 1);
        const unsigned aBase = AsU + buf*A_ST;
        const unsigned bBase = BsU + buf*B_ST;

        #pragma unroll
        for (int k8 = 0; k8 < GBK; k8 += 16) {
            unsigned af[4][4];
            #pragma unroll
            for (int mt = 0; mt < 4; mt++) {
                int row = wm*64 + mt*16 + (g & 1)*8 + l7;
                int col = k8 + (g >> 1)*8;
                ldsm4(af[mt], aBase + (row*GPAD + col)*2);
            }
            unsigned bf[4][2];
            #pragma unroll
            for (int np = 0; np < 2; np++) {
                int row = wn*32 + np*16 + (g >> 1)*8 + l7;
                int col = k8 + (g & 1)*8;
                unsigned r[4];
                ldsm4(r, bBase + (row*GPAD + col)*2);
                bf[2*np][0] = r[0]; bf[2*np][1] = r[1];
                bf[2*np+1][0] = r[2]; bf[2*np+1][1] = r[3];
            }
            #pragma unroll
            for (int mt = 0; mt < 4; mt++)
                #pragma unroll
                for (int nt = 0; nt < 4; nt++)
                    mma16(acc[mt][nt], af[mt], bf[nt]);
        }
        __syncthreads();   // all warps done with buf before it is re-filled
    }

    const int lg = lane >> 2;
    #pragma unroll
    for (int mt = 0; mt < 4; mt++) {
        const int r0 = by * 256 + wm * 64 + mt * 16 + lg;
        #pragma unroll
        for (int nt = 0; nt < 4; nt++) {
            const int c = bx * 128 + wn * 32 + nt * 8 + lt * 2;
            const float b0 = bias[c], b1 = bias[c + 1];
            if (OUT_BF16) {
                __nv_bfloat16* Cb = (__nv_bfloat16*)Cout;
                *(unsigned*)(Cb + (size_t)r0       * ldc + c) =
                    bf2pack(acc[mt][nt][0] + b0, acc[mt][nt][1] + b1);
                *(unsigned*)(Cb + (size_t)(r0 + 8) * ldc + c) =
                    bf2pack(acc[mt][nt][2] + b0, acc[mt][nt][3] + b1);
            } else {
                float* Cf = (float*)Cout;
                float2 o0, o1;
                o0.x = acc[mt][nt][0] + b0;  o0.y = acc[mt][nt][1] + b1;
                o1.x = acc[mt][nt][2] + b0;  o1.y = acc[mt][nt][3] + b1;
                *(float2*)(Cf + (size_t)r0       * ldc + c) = o0;
                *(float2*)(Cf + (size_t)(r0 + 8) * ldc + c) = o1;
            }
        }
    }
}

// ============================================================
// Flash attention (causal, GQA), bf16 mma.sync + ldmatrix.
// Q fragments register-resident; V via ldmatrix.trans;
// P converted C-frag -> A-frag in registers; K/V cp.async double-buffered.
// Block: 128 q-rows, 8 warps x 16 rows, Bc=64, E=128.
// ============================================================
#define FQP 136   // row pad in halves (272B, LDSM conflict-free)
#define FL_SMEM_BYTES ((128*FQP + 4*64*FQP) * 2)

__global__ __launch_bounds__(256)
void flash_bf16(const __nv_bfloat16* __restrict__ QKV, __nv_bfloat16* __restrict__ ctx)
{
    extern __shared__ __nv_bfloat16 sm[];
    const unsigned QsU = smem_u32(sm);
    const unsigned tileB = 64 * FQP * 2;
    const unsigned KsU = QsU + 128 * FQP * 2;
    const unsigned VsU = KsU + 2 * tileB;

    const int tid  = threadIdx.x;
    const int w    = tid >> 5, lane = tid & 31;
    const int lg   = lane >> 2, lt = lane & 3;
    const int l7   = lane & 7, g = lane >> 3;
    const int h2   = w >> 2, wq = w & 3;
    const int bh   = blockIdx.y;
    const int b    = bh / HH, h = bh % HH, kvh = h % KVH;
    const int bxr  = (int)gridDim.x - 1 - (int)blockIdx.x;   // longest first
    const int qb   = bxr * 128;
    const int qrl  = h2 * 64 + wq * 16;
    const int qr0  = qb + qrl;
    const float scale = 0.08838834764831845f;

    const __nv_bfloat16* Kg0 = QKV + (size_t)(b * LL) * QKVN + 2048 + kvh * EE;

    auto issue = [&](int buf, int kb) {
        const __nv_bfloat16* Kg = Kg0 + (size_t)kb * QKVN;
        const __nv_bfloat16* Vg = Kg + KVE;
        #pragma unroll
        for (int i = 0; i < 4; i++) {
            int q = tid + i * 256;
            int r = q >> 4, c8 = (q & 15) * 8;
            cp16(KsU + buf*tileB + (r*FQP + c8)*2, Kg + (size_t)r * QKVN + c8);
            cp16(VsU + buf*tileB + (r*FQP + c8)*2, Vg + (size_t)r * QKVN + c8);
        }
        asm volatile("cp.async.commit_group;\n");
    };

    issue(0, 0);
    {
        const __nv_bfloat16* Qg = QKV + ((size_t)(b * LL + qb)) * QKVN + h * EE;
        #pragma unroll
        for (int i = 0; i < 8; i++) {
            int q = tid + i * 256;
            int r = q >> 4, c8 = (q & 15) * 8;
            *(uint4*)(sm + r * FQP + c8) = *(const uint4*)(Qg + (size_t)r * QKVN + c8);
        }
    }
    __syncthreads();

    unsigned qf[8][4];
    #pragma unroll
    for (int e8 = 0; e8 < 8; e8++) {
        int row = qrl + (g & 1)*8 + l7;
        int col = e8*16 + (g >> 1)*8;
        ldsm4(qf[e8], QsU + (row*FQP + col)*2);
    }

    float O[16][4];
    #pragma unroll
    for (int n = 0; n < 16; n++)
        #pragma unroll
        for (int f = 0; f < 4; f++) O[n][f] = 0.f;
    float m0 = -INFINITY, m1 = -INFINITY, l0 = 0.f, l1 = 0.f;

    const int ntiles = (qb >> 6) + 2;
    for (int t = 0; t < ntiles; ++t) {
        const int kb = t * 64;
        asm volatile("cp.async.wait_group 0;\n");
        __syncthreads();
        if (t + 1 < ntiles) issue((t + 1) & 1, kb + 64);
        const int buf = t & 1;
        const unsigned kBase = KsU + buf*tileB;
        const unsigned vBase = VsU + buf*tileB;

        if (kb <= qr0 + 15) {
            float s[8][4];
            #pragma unroll
            for (int nn = 0; nn < 8; nn++)
                #pragma unroll
                for (int f = 0; f < 4; f++) s[nn][f] = 0.f;

            #pragma unroll
            for (int e8 = 0; e8 < 8; e8++) {
                #pragma unroll
                for (int np = 0; np < 4; np++) {
                    int row = np*16 + (g >> 1)*8 + l7;
                    int col = e8*16 + (g & 1)*8;
                    unsigned r[4];
                    ldsm4(r, kBase + (row*FQP + col)*2);
                    mma16(s[2*np],     qf[e8], r);
                    mma16(s[2*np + 1], qf[e8], r + 2);
                }
            }
            #pragma unroll
            for (int nn = 0; nn < 8; nn++)
                #pragma unroll
                for (int f = 0; f < 4; f++) s[nn][f] *= scale;

            if (kb + 63 > qr0) {
                const int r0g = qr0 + lg, r1g = qr0 + lg + 8;
                #pragma unroll
                for (int nn = 0; nn < 8; nn++) {
                    const int c0 = kb + nn * 8 + lt * 2;
                    if (c0     > r0g) s[nn][0] = -1e30f;
                    if (c0 + 1 > r0g) s[nn][1] = -1e30f;
                    if (c0     > r1g) s[nn][2] = -1e30f;
                    if (c0 + 1 > r1g) s[nn][3] = -1e30f;
                }
            }

            float mx0 = -1e30f, mx1 = -1e30f;
            #pragma unroll
            for (int nn = 0; nn < 8; nn++) {
                mx0 = fmaxf(mx0, fmaxf(s[nn][0], s[nn][1]));
                mx1 = fmaxf(mx1, fmaxf(s[nn][2], s[nn][3]));
            }
            mx0 = fmaxf(mx0, __shfl_xor_sync(0xFFFFFFFFu, mx0, 1));
            mx0 = fmaxf(mx0, __shfl_xor_sync(0xFFFFFFFFu, mx0, 2));
            mx1 = fmaxf(mx1, __shfl_xor_sync(0xFFFFFFFFu, mx1, 1));
            mx1 = fmaxf(mx1, __shfl_xor_sync(0xFFFFFFFFu, mx1, 2));

            const float mn0 = fmaxf(m0, mx0), mn1 = fmaxf(m1, mx1);
            const float a0 = __expf(m0 - mn0), a1 = __expf(m1 - mn1);
            float rs0 = 0.f, rs1 = 0.f;
            #pragma unroll
            for (int nn = 0; nn < 8; nn++) {
                float p0 = __expf(s[nn][0] - mn0);
                float p1 = __expf(s[nn][1] - mn0);
                float p2 = __expf(s[nn][2] - mn1);
                float p3 = __expf(s[nn][3] - mn1);
                s[nn][0] = p0; s[nn][1] = p1; s[nn][2] = p2; s[nn][3] = p3;
                rs0 += p0 + p1; rs1 += p2 + p3;
            }
            rs0 += __shfl_xor_sync(0xFFFFFFFFu, rs0, 1);
            rs0 += __shfl_xor_sync(0xFFFFFFFFu, rs0, 2);
            rs1 += __shfl_xor_sync(0xFFFFFFFFu, rs1, 1);
            rs1 += __shfl_xor_sync(0xFFFFFFFFu, rs1, 2);

            m0 = mn0; m1 = mn1;
            l0 = l0 * a0 + rs0;
            l1 = l1 * a1 + rs1;

            #pragma unroll
            for (int n = 0; n < 16; n++) {
                O[n][0] *= a0; O[n][1] *= a0;
                O[n][2] *= a1; O[n][3] *= a1;
            }

            #pragma unroll
            for (int kk = 0; kk < 4; kk++) {
                unsigned pa[4];
                pa[0] = bf2pack(s[2*kk][0],     s[2*kk][1]);
                pa[1] = bf2pack(s[2*kk][2],     s[2*kk][3]);
                pa[2] = bf2pack(s[2*kk + 1][0], s[2*kk + 1][1]);
                pa[3] = bf2pack(s[2*kk + 1][2], s[2*kk + 1][3]);
                #pragma unroll
                for (int ne = 0; ne < 8; ne++) {
                    int row = kk*16 + (g & 1)*8 + l7;
                    int col = ne*16 + (g >> 1)*8;
                    unsigned r[4];
                    ldsm4t(r, vBase + (row*FQP + col)*2);
                    mma16(O[2*ne],     pa, r);
                    mma16(O[2*ne + 1], pa, r + 2);
                }
            }
        }
    }

    const float inv0 = 1.f / l0, inv1 = 1.f / l1;
    __nv_bfloat16* Cg = ctx + ((size_t)(b * LL + qr0)) * HE + h * EE;
    #pragma unroll
    for (int n = 0; n < 16; n++) {
        const int c = n * 8 + lt * 2;
        *(unsigned*)(Cg + (size_t)lg       * HE + c) = bf2pack(O[n][0]*inv0, O[n][1]*inv0);
        *(unsigned*)(Cg + (size_t)(lg + 8) * HE + c) = bf2pack(O[n][2]*inv1, O[n][3]*inv1);
    }
}

// ============================================================
// Epilogue: out = LayerNorm(x + gelu_erf(ypre)) * gamma + beta
// ============================================================
__global__ __launch_bounds__(256)
void epilogue_ln(const float* __restrict__ x, const float* __restrict__ ypre,
                 const float* __restrict__ gamma, const float* __restrict__ beta,
                 float* __restrict__ out)
{
    const int row = blockIdx.x;
    const int tid = threadIdx.x;
    const float4* xr4 = (const float4*)(x    + (size_t)row*DD);
    const float4* yr4 = (const float4*)(ypre + (size_t)row*DD);
    float4* out4      = (float4*)(out + (size_t)row*DD);

    float4 vals[2];
    float s = 0.f, s2 = 0.f;
    #pragma unroll
    for (int k = 0; k < 2; ++k) {
        const int c = tid + k*256;
        float4 v = yr4[c];
        float4 xv = xr4[c];
        float4 r;
        r.x = xv.x + 0.5f*v.x*(1.f + erff(v.x*0.70710678118654752f));
        r.y = xv.y + 0.5f*v.y*(1.f + erff(v.y*0.70710678118654752f));
        r.z = xv.z + 0.5f*v.z*(1.f + erff(v.z*0.70710678118654752f));
        r.w = xv.w + 0.5f*v.w*(1.f + erff(v.w*0.70710678118654752f));
        vals[k] = r;
        s  += r.x + r.y + r.z + r.w;
        s2 += r.x*r.x + r.y*r.y + r.z*r.z + r.w*r.w;
    }

    __shared__ float red[2][8];
    #pragma unroll
    for (int off = 16; off > 0; off >>= 1) {
        s  += __shfl_down_sync(0xFFFFFFFFu, s,  off);
        s2 += __shfl_down_sync(0xFFFFFFFFu, s2, off);
    }
    if ((tid & 31) == 0) { red[0][tid>>5] = s; red[1][tid>>5] = s2; }
    __syncthreads();
    float ts = 0.f, ts2 = 0.f;
    #pragma unroll
    for (int w = 0; w < 8; w++) { ts += red[0][w]; ts2 += red[1][w]; }

    const float mean = ts * (1.f/2048.f);
    const float var  = ts2 * (1.f/2048.f) - mean*mean;
    const float inv  = rsqrtf(var + 1e-5f);

    const float4* g4 = (const float4*)gamma;
    const float4* b4 = (const float4*)beta;
    #pragma unroll
    for (int k = 0; k < 2; ++k) {
        const int c = tid + k*256;
        float4 gv = g4[c], bv = b4[c], r = vals[k], o;
        o.x = (r.x - mean)*inv*gv.x + bv.x;
        o.y = (r.y - mean)*inv*gv.y + bv.y;
        o.z = (r.z - mean)*inv*gv.z + bv.z;
        o.w = (r.w - mean)*inv*gv.w + bv.w;
        out4[c] = o;
    }
}

// ============================================================
// Launch
// ============================================================
extern "C" void kernel_launch(void* const* d_in, const int* in_sizes, int n_in,
                              void* d_out, int out_size)
{
    const float* x     = (const float*)d_in[0];
    const float* Wq    = (const float*)d_in[1];
    const float* bq    = (const float*)d_in[2];
    const float* Wk    = (const float*)d_in[3];
    const float* bk    = (const float*)d_in[4];
    const float* Wv    = (const float*)d_in[5];
    const float* bv    = (const float*)d_in[6];
    const float* Wo    = (const float*)d_in[7];
    const float* bo    = (const float*)d_in[8];
    const float* gamma = (const float*)d_in[9];
    const float* beta  = (const float*)d_in[10];
    float* out = (float*)d_out;

    __nv_bfloat16 *xb, *Wqkvt, *Wot, *QKV, *CTXb;
    float *bqkv, *Y;
    cudaGetSymbolAddress((void**)&xb,    g_xb);
    cudaGetSymbolAddress((void**)&Wqkvt, g_Wqkvt);
    cudaGetSymbolAddress((void**)&Wot,   g_Wot);
    cudaGetSymbolAddress((void**)&bqkv,  g_bqkv);
    cudaGetSymbolAddress((void**)&QKV,   g_QKV);
    cudaGetSymbolAddress((void**)&CTXb,  g_CTXb);
    cudaGetSymbolAddress((void**)&Y,     g_Y);

    // ---- fused operand prep (single launch) ----
    prep_all<<<PREP_BLOCKS, 256>>>(x, Wq, Wk, Wv, Wo, bq, bk, bv,
                                   xb, Wqkvt, Wot, bqkv);

    // ---- fused QKV projection (256x128 tiles, 512 threads, 4-stage) ----
    cudaFuncSetAttribute(gemm_bf16<true>,  cudaFuncAttributeMaxDynamicSharedMemorySize, GEMM_SMEM);
    cudaFuncSetAttribute(gemm_bf16<false>, cudaFuncAttributeMaxDynamicSharedMemorySize, GEMM_SMEM);
    gemm_bf16<true><<<dim3(QKVN/128, ML/256), 512, GEMM_SMEM>>>(xb, Wqkvt, bqkv, QKV,
                                                                ML, QKVN, DD, QKVN);

    // ---- causal GQA flash attention ----
    cudaFuncSetAttribute(flash_bf16, cudaFuncAttributeMaxDynamicSharedMemorySize, FL_SMEM_BYTES);
    flash_bf16<<<dim3(LL/128, BB*HH), 256, FL_SMEM_BYTES>>>(QKV, CTXb);

    // ---- output projection (fp32 out) ----
    gemm_bf16<false><<<dim3(DD/128, ML/256), 512, GEMM_SMEM>>>(CTXb, Wot, bo, Y,
                                                               ML, DD, HE, DD);

    // ---- GELU + residual + LayerNorm ----
    epilogue_ln<<<ML, 256>>>(x, Y, gamma, beta, out);
}

// round 12
// speedup vs baseline: 1.1155x; 1.1155x over previous
#include <cuda_runtime.h>
#include <cuda_bf16.h>
#include <math.h>
#include <stdint.h>

// Problem constants
#define BB   2
#define LL   2048
#define DD   2048
#define HH   16
#define KVH  4
#define EE   128
#define ML   (BB*LL)        // 4096 rows total
#define HE   (HH*EE)        // 2048
#define KVE  (KVH*EE)       // 512
#define QKVN 3072           // fused Q|K|V projection width

// -------- scratch (device globals; no allocation allowed) --------
__device__ __nv_bfloat16 g_xb[ML*DD];         // x in bf16
__device__ __nv_bfloat16 g_Wqkvt[QKVN*DD];    // [Wq|Wk|Wv]^T [N=3072][K=2048] bf16
__device__ __nv_bfloat16 g_Wot[DD*HE];        // Wo^T [N=2048][K=2048] bf16
__device__ float         g_bqkv[QKVN];        // bq|bk|bv
__device__ __nv_bfloat16 g_QKV[ML*QKVN];      // fused QKV output, row stride 3072
__device__ __nv_bfloat16 g_CTXb[ML*HE];       // attention output bf16
__device__ float         g_Y[ML*DD];          // pre-GELU O-proj output fp32

// ---------------- helpers ----------------
__device__ __forceinline__ void mma16(float* d, const unsigned* a, const unsigned* b) {
    asm volatile(
        "mma.sync.aligned.m16n8k16.row.col.f32.bf16.bf16.f32 "
        "{%0,%1,%2,%3}, {%4,%5,%6,%7}, {%8,%9}, {%0,%1,%2,%3};\n"
        : "+f"(d[0]), "+f"(d[1]), "+f"(d[2]), "+f"(d[3])
        : "r"(a[0]), "r"(a[1]), "r"(a[2]), "r"(a[3]),
          "r"(b[0]), "r"(b[1]));
}

__device__ __forceinline__ void ldsm4(unsigned* r, unsigned addr) {
    asm volatile("ldmatrix.sync.aligned.m8n8.x4.shared.b16 {%0,%1,%2,%3}, [%4];"
                 : "=r"(r[0]), "=r"(r[1]), "=r"(r[2]), "=r"(r[3]) : "r"(addr));
}

__device__ __forceinline__ void ldsm4t(unsigned* r, unsigned addr) {
    asm volatile("ldmatrix.sync.aligned.m8n8.x4.trans.shared.b16 {%0,%1,%2,%3}, [%4];"
                 : "=r"(r[0]), "=r"(r[1]), "=r"(r[2]), "=r"(r[3]) : "r"(addr));
}

__device__ __forceinline__ void cp16(unsigned smem_dst, const void* gmem_src) {
    asm volatile("cp.async.cg.shared.global [%0], [%1], 16;\n" :: "r"(smem_dst), "l"(gmem_src));
}

__device__ __forceinline__ unsigned bf2pack(float x, float y) {
    __nv_bfloat162 v = __float22bfloat162_rn(make_float2(x, y));
    return *(unsigned*)&v;
}

__device__ __forceinline__ unsigned smem_u32(const void* p) {
    unsigned a;
    asm("{ .reg .u64 t; cvta.to.shared.u64 t, %1; cvt.u32.u64 %0, t; }" : "=r"(a) : "l"(p));
    return a;
}

// ============================================================
// Fused prep kernel (single launch)
// ============================================================
#define PREP_BLOCKS 18444

__device__ __forceinline__ void transp_tile(float (*t)[33],
                                            const float* __restrict__ W,
                                            __nv_bfloat16* __restrict__ Wt,
                                            int Kd, int Nd, int bx, int by, int tid)
{
    const int n0 = bx * 32, k0 = by * 32;
    const int tx = tid & 31, ty = tid >> 5;
    #pragma unroll
    for (int i = 0; i < 4; i++)
        t[ty + 8*i][tx] = W[(size_t)(k0 + ty + 8*i) * Nd + n0 + tx];
    __syncthreads();
    #pragma unroll
    for (int i = 0; i < 4; i++)
        Wt[(size_t)(n0 + ty + 8*i) * Kd + k0 + tx] = __float2bfloat16(t[tx][ty + 8*i]);
}

__global__ __launch_bounds__(256)
void prep_all(const float* __restrict__ x,
              const float* __restrict__ Wq, const float* __restrict__ Wk,
              const float* __restrict__ Wv, const float* __restrict__ Wo,
              const float* __restrict__ bq, const float* __restrict__ bk,
              const float* __restrict__ bv,
              __nv_bfloat16* __restrict__ xb, __nv_bfloat16* __restrict__ Wqkvt,
              __nv_bfloat16* __restrict__ Wot, float* __restrict__ bqkv)
{
    __shared__ float t[32][33];
    const int bid = blockIdx.x;
    const int tid = threadIdx.x;

    if (bid < 8192) {
        int i = bid * 256 + tid;
        float4 v = ((const float4*)x)[i];
        uint2 o;
        o.x = bf2pack(v.x, v.y);
        o.y = bf2pack(v.z, v.w);
        ((uint2*)xb)[i] = o;
    } else if (bid < 12288) {
        int tt = bid - 8192;
        transp_tile(t, Wq, Wqkvt, DD, HE, tt & 63, tt >> 6, tid);
    } else if (bid < 13312) {
        int tt = bid - 12288;
        transp_tile(t, Wk, Wqkvt + (size_t)2048*DD, DD, KVE, tt & 15, tt >> 4, tid);
    } else if (bid < 14336) {
        int tt = bid - 13312;
        transp_tile(t, Wv, Wqkvt + (size_t)2560*DD, DD, KVE, tt & 15, tt >> 4, tid);
    } else if (bid < 18432) {
        int tt = bid - 14336;
        transp_tile(t, Wo, Wot, HE, DD, tt & 63, tt >> 6, tid);
    } else {
        int i = (bid - 18432) * 256 + tid;
        if (i < 2048)        bqkv[i] = bq[i];
        else if (i < 2560)   bqkv[i] = bk[i - 2048];
        else if (i < 3072)   bqkv[i] = bv[i - 2560];
    }
}

// ============================================================
// bf16 tensor-core GEMM (mma.sync + ldmatrix), 4-stage cp.async pipeline,
// CUTLASS multistage ordering (compute -> issue -> wait -> ONE sync).
// C[M,N] = A[M,K] @ W[K,N] + bias[N];  Bt = W^T [N][K] bf16.
// CTA tile 128x128, BK=32, 256 threads = 8 warps (64x32 warp tile, 2x4).
// ============================================================
#define GBK    32
#define GPAD   40                        // halves/row (80B, LDSM conflict-free)
#define T_ST   (128*GPAD*2)              // 10240 B per matrix per stage
#define GSTG   4
#define GEMM_SMEM (GSTG*2*T_ST)          // 81920 B -> 2 CTAs/SM

template<bool OUT_BF16>
__global__ __launch_bounds__(256)
void gemm_bf16(const __nv_bfloat16* __restrict__ A, const __nv_bfloat16* __restrict__ Bt,
               const float* __restrict__ bias, void* __restrict__ Cout,
               int M, int N, int K, int ldc)
{
    extern __shared__ __nv_bfloat16 gsm[];
    const unsigned AsU = smem_u32(gsm);
    const unsigned BsU = AsU + GSTG * T_ST;

    const int tid  = threadIdx.x;
    const int w    = tid >> 5, lane = tid & 31;
    const int lt   = lane & 3;
    const int l7   = lane & 7, g = lane >> 3;
    const int wm   = w & 1, wn = w >> 1;        // 2x4 warp grid
    const int bx   = blockIdx.x, by = blockIdx.y;

    const __nv_bfloat16* Ag = A  + (size_t)(by * 128) * K;
    const __nv_bfloat16* Bg = Bt + (size_t)(bx * 128) * K;

    float acc[4][4][4];
    #pragma unroll
    for (int mt = 0; mt < 4; mt++)
        #pragma unroll
        for (int nt = 0; nt < 4; nt++)
            #pragma unroll
            for (int f = 0; f < 4; f++) acc[mt][nt][f] = 0.f;

    const int KT = K / GBK;

    auto issue = [&](int kt) {
        if (kt < KT) {
            const int buf = kt & (GSTG - 1);
            const int k0 = kt * GBK;
            #pragma unroll
            for (int i = 0; i < 2; i++) {      // A: 512 chunks
                int q = tid + i * 256;
                int r = q >> 2, c8 = (q & 3) * 8;
                cp16(AsU + buf*T_ST + (r*GPAD + c8)*2, Ag + (size_t)r * K + k0 + c8);
            }
            #pragma unroll
            for (int i = 0; i < 2; i++) {      // B: 512 chunks
                int q = tid + i * 256;
                int r = q >> 2, c8 = (q & 3) * 8;
                cp16(BsU + buf*T_ST + (r*GPAD + c8)*2, Bg + (size_t)r * K + k0 + c8);
            }
        }
        asm volatile("cp.async.commit_group;\n");   // empty group past the end
    };

    // prologue: 3 stages in flight, wait for stage 0
    issue(0); issue(1); issue(2);
    asm volatile("cp.async.wait_group 2;\n");
    __syncthreads();

    for (int kt = 0; kt < KT; ++kt) {
        const int buf = kt & (GSTG - 1);
        const unsigned aBase = AsU + buf*T_ST;
        const unsigned bBase = BsU + buf*T_ST;

        #pragma unroll
        for (int k8 = 0; k8 < GBK; k8 += 16) {
            unsigned af[4][4];
            #pragma unroll
            for (int mt = 0; mt < 4; mt++) {
                int row = wm*64 + mt*16 + (g & 1)*8 + l7;
                int col = k8 + (g >> 1)*8;
                ldsm4(af[mt], aBase + (row*GPAD + col)*2);
            }
            unsigned bf[4][2];
            #pragma unroll
            for (int np = 0; np < 2; np++) {
                int row = wn*32 + np*16 + (g >> 1)*8 + l7;
                int col = k8 + (g & 1)*8;
                unsigned r[4];
                ldsm4(r, bBase + (row*GPAD + col)*2);
                bf[2*np][0] = r[0]; bf[2*np][1] = r[1];
                bf[2*np+1][0] = r[2]; bf[2*np+1][1] = r[3];
            }
            #pragma unroll
            for (int mt = 0; mt < 4; mt++)
                #pragma unroll
                for (int nt = 0; nt < 4; nt++)
                    mma16(acc[mt][nt], af[mt], bf[nt]);
        }

        // issue stage kt+3 (overwrites buf (kt-1)%4 — all warps finished it
        // before the barrier at the end of iteration kt-1), then advance.
        issue(kt + 3);
        asm volatile("cp.async.wait_group 2;\n");
        __syncthreads();
    }

    const int lg = lane >> 2;
    #pragma unroll
    for (int mt = 0; mt < 4; mt++) {
        const int r0 = by * 128 + wm * 64 + mt * 16 + lg;
        #pragma unroll
        for (int nt = 0; nt < 4; nt++) {
            const int c = bx * 128 + wn * 32 + nt * 8 + lt * 2;
            const float b0 = bias[c], b1 = bias[c + 1];
            if (OUT_BF16) {
                __nv_bfloat16* Cb = (__nv_bfloat16*)Cout;
                *(unsigned*)(Cb + (size_t)r0       * ldc + c) =
                    bf2pack(acc[mt][nt][0] + b0, acc[mt][nt][1] + b1);
                *(unsigned*)(Cb + (size_t)(r0 + 8) * ldc + c) =
                    bf2pack(acc[mt][nt][2] + b0, acc[mt][nt][3] + b1);
            } else {
                float* Cf = (float*)Cout;
                float2 o0, o1;
                o0.x = acc[mt][nt][0] + b0;  o0.y = acc[mt][nt][1] + b1;
                o1.x = acc[mt][nt][2] + b0;  o1.y = acc[mt][nt][3] + b1;
                *(float2*)(Cf + (size_t)r0       * ldc + c) = o0;
                *(float2*)(Cf + (size_t)(r0 + 8) * ldc + c) = o1;
            }
        }
    }
}

// ============================================================
// Flash attention (causal, GQA), bf16 mma.sync + ldmatrix.
// Q fragments register-resident; V via ldmatrix.trans;
// P converted C-frag -> A-frag in registers; K/V cp.async double-buffered.
// Block: 128 q-rows, 8 warps x 16 rows, Bc=64, E=128.
// ============================================================
#define FQP 136   // row pad in halves (272B, LDSM conflict-free)
#define FL_SMEM_BYTES ((128*FQP + 4*64*FQP) * 2)

__global__ __launch_bounds__(256)
void flash_bf16(const __nv_bfloat16* __restrict__ QKV, __nv_bfloat16* __restrict__ ctx)
{
    extern __shared__ __nv_bfloat16 sm[];
    const unsigned QsU = smem_u32(sm);
    const unsigned tileB = 64 * FQP * 2;
    const unsigned KsU = QsU + 128 * FQP * 2;
    const unsigned VsU = KsU + 2 * tileB;

    const int tid  = threadIdx.x;
    const int w    = tid >> 5, lane = tid & 31;
    const int lg   = lane >> 2, lt = lane & 3;
    const int l7   = lane & 7, g = lane >> 3;
    const int h2   = w >> 2, wq = w & 3;
    const int bh   = blockIdx.y;
    const int b    = bh / HH, h = bh % HH, kvh = h % KVH;
    const int bxr  = (int)gridDim.x - 1 - (int)blockIdx.x;   // longest first
    const int qb   = bxr * 128;
    const int qrl  = h2 * 64 + wq * 16;
    const int qr0  = qb + qrl;
    const float scale = 0.08838834764831845f;

    const __nv_bfloat16* Kg0 = QKV + (size_t)(b * LL) * QKVN + 2048 + kvh * EE;

    auto issue = [&](int buf, int kb) {
        const __nv_bfloat16* Kg = Kg0 + (size_t)kb * QKVN;
        const __nv_bfloat16* Vg = Kg + KVE;
        #pragma unroll
        for (int i = 0; i < 4; i++) {
            int q = tid + i * 256;
            int r = q >> 4, c8 = (q & 15) * 8;
            cp16(KsU + buf*tileB + (r*FQP + c8)*2, Kg + (size_t)r * QKVN + c8);
            cp16(VsU + buf*tileB + (r*FQP + c8)*2, Vg + (size_t)r * QKVN + c8);
        }
        asm volatile("cp.async.commit_group;\n");
    };

    issue(0, 0);
    {
        const __nv_bfloat16* Qg = QKV + ((size_t)(b * LL + qb)) * QKVN + h * EE;
        #pragma unroll
        for (int i = 0; i < 8; i++) {
            int q = tid + i * 256;
            int r = q >> 4, c8 = (q & 15) * 8;
            *(uint4*)(sm + r * FQP + c8) = *(const uint4*)(Qg + (size_t)r * QKVN + c8);
        }
    }
    __syncthreads();

    unsigned qf[8][4];
    #pragma unroll
    for (int e8 = 0; e8 < 8; e8++) {
        int row = qrl + (g & 1)*8 + l7;
        int col = e8*16 + (g >> 1)*8;
        ldsm4(qf[e8], QsU + (row*FQP + col)*2);
    }

    float O[16][4];
    #pragma unroll
    for (int n = 0; n < 16; n++)
        #pragma unroll
        for (int f = 0; f < 4; f++) O[n][f] = 0.f;
    float m0 = -INFINITY, m1 = -INFINITY, l0 = 0.f, l1 = 0.f;

    const int ntiles = (qb >> 6) + 2;
    for (int t = 0; t < ntiles; ++t) {
        const int kb = t * 64;
        asm volatile("cp.async.wait_group 0;\n");
        __syncthreads();
        if (t + 1 < ntiles) issue((t + 1) & 1, kb + 64);
        const int buf = t & 1;
        const unsigned kBase = KsU + buf*tileB;
        const unsigned vBase = VsU + buf*tileB;

        if (kb <= qr0 + 15) {
            float s[8][4];
            #pragma unroll
            for (int nn = 0; nn < 8; nn++)
                #pragma unroll
                for (int f = 0; f < 4; f++) s[nn][f] = 0.f;

            #pragma unroll
            for (int e8 = 0; e8 < 8; e8++) {
                #pragma unroll
                for (int np = 0; np < 4; np++) {
                    int row = np*16 + (g >> 1)*8 + l7;
                    int col = e8*16 + (g & 1)*8;
                    unsigned r[4];
                    ldsm4(r, kBase + (row*FQP + col)*2);
                    mma16(s[2*np],     qf[e8], r);
                    mma16(s[2*np + 1], qf[e8], r + 2);
                }
            }
            #pragma unroll
            for (int nn = 0; nn < 8; nn++)
                #pragma unroll
                for (int f = 0; f < 4; f++) s[nn][f] *= scale;

            if (kb + 63 > qr0) {
                const int r0g = qr0 + lg, r1g = qr0 + lg + 8;
                #pragma unroll
                for (int nn = 0; nn < 8; nn++) {
                    const int c0 = kb + nn * 8 + lt * 2;
                    if (c0     > r0g) s[nn][0] = -1e30f;
                    if (c0 + 1 > r0g) s[nn][1] = -1e30f;
                    if (c0     > r1g) s[nn][2] = -1e30f;
                    if (c0 + 1 > r1g) s[nn][3] = -1e30f;
                }
            }

            float mx0 = -1e30f, mx1 = -1e30f;
            #pragma unroll
            for (int nn = 0; nn < 8; nn++) {
                mx0 = fmaxf(mx0, fmaxf(s[nn][0], s[nn][1]));
                mx1 = fmaxf(mx1, fmaxf(s[nn][2], s[nn][3]));
            }
            mx0 = fmaxf(mx0, __shfl_xor_sync(0xFFFFFFFFu, mx0, 1));
            mx0 = fmaxf(mx0, __shfl_xor_sync(0xFFFFFFFFu, mx0, 2));
            mx1 = fmaxf(mx1, __shfl_xor_sync(0xFFFFFFFFu, mx1, 1));
            mx1 = fmaxf(mx1, __shfl_xor_sync(0xFFFFFFFFu, mx1, 2));

            const float mn0 = fmaxf(m0, mx0), mn1 = fmaxf(m1, mx1);
            const float a0 = __expf(m0 - mn0), a1 = __expf(m1 - mn1);
            float rs0 = 0.f, rs1 = 0.f;
            #pragma unroll
            for (int nn = 0; nn < 8; nn++) {
                float p0 = __expf(s[nn][0] - mn0);
                float p1 = __expf(s[nn][1] - mn0);
                float p2 = __expf(s[nn][2] - mn1);
                float p3 = __expf(s[nn][3] - mn1);
                s[nn][0] = p0; s[nn][1] = p1; s[nn][2] = p2; s[nn][3] = p3;
                rs0 += p0 + p1; rs1 += p2 + p3;
            }
            rs0 += __shfl_xor_sync(0xFFFFFFFFu, rs0, 1);
            rs0 += __shfl_xor_sync(0xFFFFFFFFu, rs0, 2);
            rs1 += __shfl_xor_sync(0xFFFFFFFFu, rs1, 1);
            rs1 += __shfl_xor_sync(0xFFFFFFFFu, rs1, 2);

            m0 = mn0; m1 = mn1;
            l0 = l0 * a0 + rs0;
            l1 = l1 * a1 + rs1;

            #pragma unroll
            for (int n = 0; n < 16; n++) {
                O[n][0] *= a0; O[n][1] *= a0;
                O[n][2] *= a1; O[n][3] *= a1;
            }

            #pragma unroll
            for (int kk = 0; kk < 4; kk++) {
                unsigned pa[4];
                pa[0] = bf2pack(s[2*kk][0],     s[2*kk][1]);
                pa[1] = bf2pack(s[2*kk][2],     s[2*kk][3]);
                pa[2] = bf2pack(s[2*kk + 1][0], s[2*kk + 1][1]);
                pa[3] = bf2pack(s[2*kk + 1][2], s[2*kk + 1][3]);
                #pragma unroll
                for (int ne = 0; ne < 8; ne++) {
                    int row = kk*16 + (g & 1)*8 + l7;
                    int col = ne*16 + (g >> 1)*8;
                    unsigned r[4];
                    ldsm4t(r, vBase + (row*FQP + col)*2);
                    mma16(O[2*ne],     pa, r);
                    mma16(O[2*ne + 1], pa, r + 2);
                }
            }
        }
    }

    const float inv0 = 1.f / l0, inv1 = 1.f / l1;
    __nv_bfloat16* Cg = ctx + ((size_t)(b * LL + qr0)) * HE + h * EE;
    #pragma unroll
    for (int n = 0; n < 16; n++) {
        const int c = n * 8 + lt * 2;
        *(unsigned*)(Cg + (size_t)lg       * HE + c) = bf2pack(O[n][0]*inv0, O[n][1]*inv0);
        *(unsigned*)(Cg + (size_t)(lg + 8) * HE + c) = bf2pack(O[n][2]*inv1, O[n][3]*inv1);
    }
}

// ============================================================
// Epilogue: out = LayerNorm(x + gelu_erf(ypre)) * gamma + beta
// ============================================================
__global__ __launch_bounds__(256)
void epilogue_ln(const float* __restrict__ x, const float* __restrict__ ypre,
                 const float* __restrict__ gamma, const float* __restrict__ beta,
                 float* __restrict__ out)
{
    const int row = blockIdx.x;
    const int tid = threadIdx.x;
    const float4* xr4 = (const float4*)(x    + (size_t)row*DD);
    const float4* yr4 = (const float4*)(ypre + (size_t)row*DD);
    float4* out4      = (float4*)(out + (size_t)row*DD);

    float4 vals[2];
    float s = 0.f, s2 = 0.f;
    #pragma unroll
    for (int k = 0; k < 2; ++k) {
        const int c = tid + k*256;
        float4 v = yr4[c];
        float4 xv = xr4[c];
        float4 r;
        r.x = xv.x + 0.5f*v.x*(1.f + erff(v.x*0.70710678118654752f));
        r.y = xv.y + 0.5f*v.y*(1.f + erff(v.y*0.70710678118654752f));
        r.z = xv.z + 0.5f*v.z*(1.f + erff(v.z*0.70710678118654752f));
        r.w = xv.w + 0.5f*v.w*(1.f + erff(v.w*0.70710678118654752f));
        vals[k] = r;
        s  += r.x + r.y + r.z + r.w;
        s2 += r.x*r.x + r.y*r.y + r.z*r.z + r.w*r.w;
    }

    __shared__ float red[2][8];
    #pragma unroll
    for (int off = 16; off > 0; off >>= 1) {
        s  += __shfl_down_sync(0xFFFFFFFFu, s,  off);
        s2 += __shfl_down_sync(0xFFFFFFFFu, s2, off);
    }
    if ((tid & 31) == 0) { red[0][tid>>5] = s; red[1][tid>>5] = s2; }
    __syncthreads();
    float ts = 0.f, ts2 = 0.f;
    #pragma unroll
    for (int w = 0; w < 8; w++) { ts += red[0][w]; ts2 += red[1][w]; }

    const float mean = ts * (1.f/2048.f);
    const float var  = ts2 * (1.f/2048.f) - mean*mean;
    const float inv  = rsqrtf(var + 1e-5f);

    const float4* g4 = (const float4*)gamma;
    const float4* b4 = (const float4*)beta;
    #pragma unroll
    for (int k = 0; k < 2; ++k) {
        const int c = tid + k*256;
        float4 gv = g4[c], bv = b4[c], r = vals[k], o;
        o.x = (r.x - mean)*inv*gv.x + bv.x;
        o.y = (r.y - mean)*inv*gv.y + bv.y;
        o.z = (r.z - mean)*inv*gv.z + bv.z;
        o.w = (r.w - mean)*inv*gv.w + bv.w;
        out4[c] = o;
    }
}

// ============================================================
// Launch
// ============================================================
extern "C" void kernel_launch(void* const* d_in, const int* in_sizes, int n_in,
                              void* d_out, int out_size)
{
    const float* x     = (const float*)d_in[0];
    const float* Wq    = (const float*)d_in[1];
    const float* bq    = (const float*)d_in[2];
    const float* Wk    = (const float*)d_in[3];
    const float* bk    = (const float*)d_in[4];
    const float* Wv    = (const float*)d_in[5];
    const float* bv    = (const float*)d_in[6];
    const float* Wo    = (const float*)d_in[7];
    const float* bo    = (const float*)d_in[8];
    const float* gamma = (const float*)d_in[9];
    const float* beta  = (const float*)d_in[10];
    float* out = (float*)d_out;

    __nv_bfloat16 *xb, *Wqkvt, *Wot, *QKV, *CTXb;
    float *bqkv, *Y;
    cudaGetSymbolAddress((void**)&xb,    g_xb);
    cudaGetSymbolAddress((void**)&Wqkvt, g_Wqkvt);
    cudaGetSymbolAddress((void**)&Wot,   g_Wot);
    cudaGetSymbolAddress((void**)&bqkv,  g_bqkv);
    cudaGetSymbolAddress((void**)&QKV,   g_QKV);
    cudaGetSymbolAddress((void**)&CTXb,  g_CTXb);
    cudaGetSymbolAddress((void**)&Y,     g_Y);

    // ---- fused operand prep (single launch) ----
    prep_all<<<PREP_BLOCKS, 256>>>(x, Wq, Wk, Wv, Wo, bq, bk, bv,
                                   xb, Wqkvt, Wot, bqkv);

    // ---- fused QKV projection (128x128 tiles, 256 threads, 4-stage) ----
    cudaFuncSetAttribute(gemm_bf16<true>,  cudaFuncAttributeMaxDynamicSharedMemorySize, GEMM_SMEM);
    cudaFuncSetAttribute(gemm_bf16<false>, cudaFuncAttributeMaxDynamicSharedMemorySize, GEMM_SMEM);
    gemm_bf16<true><<<dim3(QKVN/128, ML/128), 256, GEMM_SMEM>>>(xb, Wqkvt, bqkv, QKV,
                                                                ML, QKVN, DD, QKVN);

    // ---- causal GQA flash attention ----
    cudaFuncSetAttribute(flash_bf16, cudaFuncAttributeMaxDynamicSharedMemorySize, FL_SMEM_BYTES);
    flash_bf16<<<dim3(LL/128, BB*HH), 256, FL_SMEM_BYTES>>>(QKV, CTXb);

    // ---- output projection (fp32 out) ----
    gemm_bf16<false><<<dim3(DD/128, ML/128), 256, GEMM_SMEM>>>(CTXb, Wot, bo, Y,
                                                               ML, DD, HE, DD);

    // ---- GELU + residual + LayerNorm ----
    epilogue_ln<<<ML, 256>>>(x, Y, gamma, beta, out);
}

// round 13
// speedup vs baseline: 1.1830x; 1.0605x over previous
#include <cuda_runtime.h>
#include <cuda_bf16.h>
#include <math.h>
#include <stdint.h>

// Problem constants
#define BB   2
#define LL   2048
#define DD   2048
#define HH   16
#define KVH  4
#define EE   128
#define ML   (BB*LL)        // 4096 rows total
#define HE   (HH*EE)        // 2048
#define KVE  (KVH*EE)       // 512
#define QKVN 3072           // fused Q|K|V projection width

// -------- scratch (device globals; no allocation allowed) --------
__device__ __nv_bfloat16 g_xb[ML*DD];         // x in bf16
__device__ __nv_bfloat16 g_Wqkvt[QKVN*DD];    // [Wq|Wk|Wv]^T [N=3072][K=2048] bf16
__device__ __nv_bfloat16 g_Wot[DD*HE];        // Wo^T [N=2048][K=2048] bf16
__device__ float         g_bqkv[QKVN];        // bq|bk|bv
__device__ __nv_bfloat16 g_QKV[ML*QKVN];      // fused QKV output, row stride 3072
__device__ __nv_bfloat16 g_CTXb[ML*HE];       // attention output bf16
__device__ float         g_Y[ML*DD];          // pre-GELU O-proj output fp32

// ---------------- helpers ----------------
__device__ __forceinline__ void mma16(float* d, const unsigned* a, const unsigned* b) {
    asm volatile(
        "mma.sync.aligned.m16n8k16.row.col.f32.bf16.bf16.f32 "
        "{%0,%1,%2,%3}, {%4,%5,%6,%7}, {%8,%9}, {%0,%1,%2,%3};\n"
        : "+f"(d[0]), "+f"(d[1]), "+f"(d[2]), "+f"(d[3])
        : "r"(a[0]), "r"(a[1]), "r"(a[2]), "r"(a[3]),
          "r"(b[0]), "r"(b[1]));
}

__device__ __forceinline__ void ldsm4(unsigned* r, unsigned addr) {
    asm volatile("ldmatrix.sync.aligned.m8n8.x4.shared.b16 {%0,%1,%2,%3}, [%4];"
                 : "=r"(r[0]), "=r"(r[1]), "=r"(r[2]), "=r"(r[3]) : "r"(addr));
}

__device__ __forceinline__ void ldsm4t(unsigned* r, unsigned addr) {
    asm volatile("ldmatrix.sync.aligned.m8n8.x4.trans.shared.b16 {%0,%1,%2,%3}, [%4];"
                 : "=r"(r[0]), "=r"(r[1]), "=r"(r[2]), "=r"(r[3]) : "r"(addr));
}

__device__ __forceinline__ void cp16(unsigned smem_dst, const void* gmem_src) {
    asm volatile("cp.async.cg.shared.global [%0], [%1], 16;\n" :: "r"(smem_dst), "l"(gmem_src));
}

__device__ __forceinline__ unsigned bf2pack(float x, float y) {
    __nv_bfloat162 v = __float22bfloat162_rn(make_float2(x, y));
    return *(unsigned*)&v;
}

__device__ __forceinline__ unsigned smem_u32(const void* p) {
    unsigned a;
    asm("{ .reg .u64 t; cvta.to.shared.u64 t, %1; cvt.u32.u64 %0, t; }" : "=r"(a) : "l"(p));
    return a;
}

// ============================================================
// Fused prep kernel (single launch)
// ============================================================
#define PREP_BLOCKS 18444

__device__ __forceinline__ void transp_tile(float (*t)[33],
                                            const float* __restrict__ W,
                                            __nv_bfloat16* __restrict__ Wt,
                                            int Kd, int Nd, int bx, int by, int tid)
{
    const int n0 = bx * 32, k0 = by * 32;
    const int tx = tid & 31, ty = tid >> 5;
    #pragma unroll
    for (int i = 0; i < 4; i++)
        t[ty + 8*i][tx] = W[(size_t)(k0 + ty + 8*i) * Nd + n0 + tx];
    __syncthreads();
    #pragma unroll
    for (int i = 0; i < 4; i++)
        Wt[(size_t)(n0 + ty + 8*i) * Kd + k0 + tx] = __float2bfloat16(t[tx][ty + 8*i]);
}

__global__ __launch_bounds__(256)
void prep_all(const float* __restrict__ x,
              const float* __restrict__ Wq, const float* __restrict__ Wk,
              const float* __restrict__ Wv, const float* __restrict__ Wo,
              const float* __restrict__ bq, const float* __restrict__ bk,
              const float* __restrict__ bv,
              __nv_bfloat16* __restrict__ xb, __nv_bfloat16* __restrict__ Wqkvt,
              __nv_bfloat16* __restrict__ Wot, float* __restrict__ bqkv)
{
    __shared__ float t[32][33];
    const int bid = blockIdx.x;
    const int tid = threadIdx.x;

    if (bid < 8192) {
        int i = bid * 256 + tid;
        float4 v = ((const float4*)x)[i];
        uint2 o;
        o.x = bf2pack(v.x, v.y);
        o.y = bf2pack(v.z, v.w);
        ((uint2*)xb)[i] = o;
    } else if (bid < 12288) {
        int tt = bid - 8192;
        transp_tile(t, Wq, Wqkvt, DD, HE, tt & 63, tt >> 6, tid);
    } else if (bid < 13312) {
        int tt = bid - 12288;
        transp_tile(t, Wk, Wqkvt + (size_t)2048*DD, DD, KVE, tt & 15, tt >> 4, tid);
    } else if (bid < 14336) {
        int tt = bid - 13312;
        transp_tile(t, Wv, Wqkvt + (size_t)2560*DD, DD, KVE, tt & 15, tt >> 4, tid);
    } else if (bid < 18432) {
        int tt = bid - 14336;
        transp_tile(t, Wo, Wot, HE, DD, tt & 63, tt >> 6, tid);
    } else {
        int i = (bid - 18432) * 256 + tid;
        if (i < 2048)        bqkv[i] = bq[i];
        else if (i < 2560)   bqkv[i] = bk[i - 2048];
        else if (i < 3072)   bqkv[i] = bv[i - 2560];
    }
}

// ============================================================
// bf16 tensor-core GEMM: mma.sync + ldmatrix, 4-stage cp.async pipeline
// AND register-level fragment double buffering (LDSM k16-step i+1 in
// flight while MMAs of step i execute).
// C[M,N] = A[M,K] @ W[K,N] + bias[N];  Bt = W^T [N][K] bf16.
// CTA tile 128x128, BK=32, 256 threads = 8 warps (64x32 warp tile, 2x4).
// ============================================================
#define GBK    32
#define GPAD   40                        // halves/row (80B, LDSM conflict-free)
#define T_ST   (128*GPAD*2)              // 10240 B per matrix per stage
#define GSTG   4
#define GEMM_SMEM (GSTG*2*T_ST)          // 81920 B -> 2 CTAs/SM

template<bool OUT_BF16>
__global__ __launch_bounds__(256, 2)
void gemm_bf16(const __nv_bfloat16* __restrict__ A, const __nv_bfloat16* __restrict__ Bt,
               const float* __restrict__ bias, void* __restrict__ Cout,
               int M, int N, int K, int ldc)
{
    extern __shared__ __nv_bfloat16 gsm[];
    const unsigned AsU = smem_u32(gsm);
    const unsigned BsU = AsU + GSTG * T_ST;

    const int tid  = threadIdx.x;
    const int w    = tid >> 5, lane = tid & 31;
    const int lt   = lane & 3;
    const int l7   = lane & 7, g = lane >> 3;
    const int wm   = w & 1, wn = w >> 1;        // 2x4 warp grid
    const int bx   = blockIdx.x, by = blockIdx.y;

    const __nv_bfloat16* Ag = A  + (size_t)(by * 128) * K;
    const __nv_bfloat16* Bg = Bt + (size_t)(bx * 128) * K;

    float acc[4][4][4];
    #pragma unroll
    for (int mt = 0; mt < 4; mt++)
        #pragma unroll
        for (int nt = 0; nt < 4; nt++)
            #pragma unroll
            for (int f = 0; f < 4; f++) acc[mt][nt][f] = 0.f;

    const int KT = K / GBK;

    auto issue = [&](int kt) {
        if (kt < KT) {
            const int buf = kt & (GSTG - 1);
            const int k0 = kt * GBK;
            #pragma unroll
            for (int i = 0; i < 2; i++) {      // A: 512 chunks
                int q = tid + i * 256;
                int r = q >> 2, c8 = (q & 3) * 8;
                cp16(AsU + buf*T_ST + (r*GPAD + c8)*2, Ag + (size_t)r * K + k0 + c8);
            }
            #pragma unroll
            for (int i = 0; i < 2; i++) {      // B: 512 chunks
                int q = tid + i * 256;
                int r = q >> 2, c8 = (q & 3) * 8;
                cp16(BsU + buf*T_ST + (r*GPAD + c8)*2, Bg + (size_t)r * K + k0 + c8);
            }
        }
        asm volatile("cp.async.commit_group;\n");   // empty group past the end
    };

    // fragment loaders: frag set for (buffer base, k16-column offset)
    const int arow = wm*64 + (g & 1)*8 + l7;
    const int acol = (g >> 1)*8;
    const int brow0 = wn*32 + (g >> 1)*8 + l7;       // np=0
    const int brow1 = wn*32 + 16 + (g >> 1)*8 + l7;  // np=1
    const int bcol = (g & 1)*8;

    auto load_frags = [&](unsigned aBase, unsigned bBase, int k8,
                          unsigned (&af)[4][4], unsigned (&bf)[4][2]) {
        #pragma unroll
        for (int mt = 0; mt < 4; mt++)
            ldsm4(af[mt], aBase + ((arow + mt*16)*GPAD + k8 + acol)*2);
        unsigned r0[4], r1[4];
        ldsm4(r0, bBase + (brow0*GPAD + k8 + bcol)*2);
        ldsm4(r1, bBase + (brow1*GPAD + k8 + bcol)*2);
        bf[0][0] = r0[0]; bf[0][1] = r0[1];
        bf[1][0] = r0[2]; bf[1][1] = r0[3];
        bf[2][0] = r1[0]; bf[2][1] = r1[1];
        bf[3][0] = r1[2]; bf[3][1] = r1[3];
    };

    auto mma_block = [&](const unsigned (&af)[4][4], const unsigned (&bf)[4][2]) {
        #pragma unroll
        for (int mt = 0; mt < 4; mt++)
            #pragma unroll
            for (int nt = 0; nt < 4; nt++)
                mma16(acc[mt][nt], af[mt], bf[nt]);
    };

    // prologue: 3 stages in flight, wait for stage 0, preload first frags
    issue(0); issue(1); issue(2);
    asm volatile("cp.async.wait_group 2;\n");
    __syncthreads();

    unsigned afA[4][4], bfA[4][2];   // current k16 step
    unsigned afB[4][4], bfB[4][2];   // next k16 step
    load_frags(AsU, BsU, 0, afA, bfA);

    for (int kt = 0; kt < KT; ++kt) {
        const int buf = kt & (GSTG - 1);
        const unsigned aBase = AsU + buf*T_ST;
        const unsigned bBase = BsU + buf*T_ST;

        // prefetch frags for second half of this tile, then compute first half
        load_frags(aBase, bBase, 16, afB, bfB);
        mma_block(afA, bfA);

        // refill stage kt+3 (buffer (kt-1)%4 — last read before the previous
        // iteration's barrier), then make buffer kt+1 visible.
        issue(kt + 3);
        asm volatile("cp.async.wait_group 2;\n");
        __syncthreads();

        // prefetch frags for next tile's first half, compute second half
        const int nbuf = (kt + 1) & (GSTG - 1);
        load_frags(AsU + nbuf*T_ST, BsU + nbuf*T_ST, 0, afA, bfA);
        mma_block(afB, bfB);
    }

    const int lg = lane >> 2;
    #pragma unroll
    for (int mt = 0; mt < 4; mt++) {
        const int r0 = by * 128 + wm * 64 + mt * 16 + lg;
        #pragma unroll
        for (int nt = 0; nt < 4; nt++) {
            const int c = bx * 128 + wn * 32 + nt * 8 + lt * 2;
            const float b0 = bias[c], b1 = bias[c + 1];
            if (OUT_BF16) {
                __nv_bfloat16* Cb = (__nv_bfloat16*)Cout;
                *(unsigned*)(Cb + (size_t)r0       * ldc + c) =
                    bf2pack(acc[mt][nt][0] + b0, acc[mt][nt][1] + b1);
                *(unsigned*)(Cb + (size_t)(r0 + 8) * ldc + c) =
                    bf2pack(acc[mt][nt][2] + b0, acc[mt][nt][3] + b1);
            } else {
                float* Cf = (float*)Cout;
                float2 o0, o1;
                o0.x = acc[mt][nt][0] + b0;  o0.y = acc[mt][nt][1] + b1;
                o1.x = acc[mt][nt][2] + b0;  o1.y = acc[mt][nt][3] + b1;
                *(float2*)(Cf + (size_t)r0       * ldc + c) = o0;
                *(float2*)(Cf + (size_t)(r0 + 8) * ldc + c) = o1;
            }
        }
    }
}

// ============================================================
// Flash attention (causal, GQA), bf16 mma.sync + ldmatrix.
// Q fragments register-resident; V via ldmatrix.trans;
// P converted C-frag -> A-frag in registers; K/V cp.async double-buffered.
// Block: 128 q-rows, 8 warps x 16 rows, Bc=64, E=128.
// ============================================================
#define FQP 136   // row pad in halves (272B, LDSM conflict-free)
#define FL_SMEM_BYTES ((128*FQP + 4*64*FQP) * 2)

__global__ __launch_bounds__(256)
void flash_bf16(const __nv_bfloat16* __restrict__ QKV, __nv_bfloat16* __restrict__ ctx)
{
    extern __shared__ __nv_bfloat16 sm[];
    const unsigned QsU = smem_u32(sm);
    const unsigned tileB = 64 * FQP * 2;
    const unsigned KsU = QsU + 128 * FQP * 2;
    const unsigned VsU = KsU + 2 * tileB;

    const int tid  = threadIdx.x;
    const int w    = tid >> 5, lane = tid & 31;
    const int lg   = lane >> 2, lt = lane & 3;
    const int l7   = lane & 7, g = lane >> 3;
    const int h2   = w >> 2, wq = w & 3;
    const int bh   = blockIdx.y;
    const int b    = bh / HH, h = bh % HH, kvh = h % KVH;
    const int bxr  = (int)gridDim.x - 1 - (int)blockIdx.x;   // longest first
    const int qb   = bxr * 128;
    const int qrl  = h2 * 64 + wq * 16;
    const int qr0  = qb + qrl;
    const float scale = 0.08838834764831845f;

    const __nv_bfloat16* Kg0 = QKV + (size_t)(b * LL) * QKVN + 2048 + kvh * EE;

    auto issue = [&](int buf, int kb) {
        const __nv_bfloat16* Kg = Kg0 + (size_t)kb * QKVN;
        const __nv_bfloat16* Vg = Kg + KVE;
        #pragma unroll
        for (int i = 0; i < 4; i++) {
            int q = tid + i * 256;
            int r = q >> 4, c8 = (q & 15) * 8;
            cp16(KsU + buf*tileB + (r*FQP + c8)*2, Kg + (size_t)r * QKVN + c8);
            cp16(VsU + buf*tileB + (r*FQP + c8)*2, Vg + (size_t)r * QKVN + c8);
        }
        asm volatile("cp.async.commit_group;\n");
    };

    issue(0, 0);
    {
        const __nv_bfloat16* Qg = QKV + ((size_t)(b * LL + qb)) * QKVN + h * EE;
        #pragma unroll
        for (int i = 0; i < 8; i++) {
            int q = tid + i * 256;
            int r = q >> 4, c8 = (q & 15) * 8;
            *(uint4*)(sm + r * FQP + c8) = *(const uint4*)(Qg + (size_t)r * QKVN + c8);
        }
    }
    __syncthreads();

    unsigned qf[8][4];
    #pragma unroll
    for (int e8 = 0; e8 < 8; e8++) {
        int row = qrl + (g & 1)*8 + l7;
        int col = e8*16 + (g >> 1)*8;
        ldsm4(qf[e8], QsU + (row*FQP + col)*2);
    }

    float O[16][4];
    #pragma unroll
    for (int n = 0; n < 16; n++)
        #pragma unroll
        for (int f = 0; f < 4; f++) O[n][f] = 0.f;
    float m0 = -INFINITY, m1 = -INFINITY, l0 = 0.f, l1 = 0.f;

    const int ntiles = (qb >> 6) + 2;
    for (int t = 0; t < ntiles; ++t) {
        const int kb = t * 64;
        asm volatile("cp.async.wait_group 0;\n");
        __syncthreads();
        if (t + 1 < ntiles) issue((t + 1) & 1, kb + 64);
        const int buf = t & 1;
        const unsigned kBase = KsU + buf*tileB;
        const unsigned vBase = VsU + buf*tileB;

        if (kb <= qr0 + 15) {
            float s[8][4];
            #pragma unroll
            for (int nn = 0; nn < 8; nn++)
                #pragma unroll
                for (int f = 0; f < 4; f++) s[nn][f] = 0.f;

            #pragma unroll
            for (int e8 = 0; e8 < 8; e8++) {
                #pragma unroll
                for (int np = 0; np < 4; np++) {
                    int row = np*16 + (g >> 1)*8 + l7;
                    int col = e8*16 + (g & 1)*8;
                    unsigned r[4];
                    ldsm4(r, kBase + (row*FQP + col)*2);
                    mma16(s[2*np],     qf[e8], r);
                    mma16(s[2*np + 1], qf[e8], r + 2);
                }
            }
            #pragma unroll
            for (int nn = 0; nn < 8; nn++)
                #pragma unroll
                for (int f = 0; f < 4; f++) s[nn][f] *= scale;

            if (kb + 63 > qr0) {
                const int r0g = qr0 + lg, r1g = qr0 + lg + 8;
                #pragma unroll
                for (int nn = 0; nn < 8; nn++) {
                    const int c0 = kb + nn * 8 + lt * 2;
                    if (c0     > r0g) s[nn][0] = -1e30f;
                    if (c0 + 1 > r0g) s[nn][1] = -1e30f;
                    if (c0     > r1g) s[nn][2] = -1e30f;
                    if (c0 + 1 > r1g) s[nn][3] = -1e30f;
                }
            }

            float mx0 = -1e30f, mx1 = -1e30f;
            #pragma unroll
            for (int nn = 0; nn < 8; nn++) {
                mx0 = fmaxf(mx0, fmaxf(s[nn][0], s[nn][1]));
                mx1 = fmaxf(mx1, fmaxf(s[nn][2], s[nn][3]));
            }
            mx0 = fmaxf(mx0, __shfl_xor_sync(0xFFFFFFFFu, mx0, 1));
            mx0 = fmaxf(mx0, __shfl_xor_sync(0xFFFFFFFFu, mx0, 2));
            mx1 = fmaxf(mx1, __shfl_xor_sync(0xFFFFFFFFu, mx1, 1));
            mx1 = fmaxf(mx1, __shfl_xor_sync(0xFFFFFFFFu, mx1, 2));

            const float mn0 = fmaxf(m0, mx0), mn1 = fmaxf(m1, mx1);
            const float a0 = __expf(m0 - mn0), a1 = __expf(m1 - mn1);
            float rs0 = 0.f, rs1 = 0.f;
            #pragma unroll
            for (int nn = 0; nn < 8; nn++) {
                float p0 = __expf(s[nn][0] - mn0);
                float p1 = __expf(s[nn][1] - mn0);
                float p2 = __expf(s[nn][2] - mn1);
                float p3 = __expf(s[nn][3] - mn1);
                s[nn][0] = p0; s[nn][1] = p1; s[nn][2] = p2; s[nn][3] = p3;
                rs0 += p0 + p1; rs1 += p2 + p3;
            }
            rs0 += __shfl_xor_sync(0xFFFFFFFFu, rs0, 1);
            rs0 += __shfl_xor_sync(0xFFFFFFFFu, rs0, 2);
            rs1 += __shfl_xor_sync(0xFFFFFFFFu, rs1, 1);
            rs1 += __shfl_xor_sync(0xFFFFFFFFu, rs1, 2);

            m0 = mn0; m1 = mn1;
            l0 = l0 * a0 + rs0;
            l1 = l1 * a1 + rs1;

            #pragma unroll
            for (int n = 0; n < 16; n++) {
                O[n][0] *= a0; O[n][1] *= a0;
                O[n][2] *= a1; O[n][3] *= a1;
            }

            #pragma unroll
            for (int kk = 0; kk < 4; kk++) {
                unsigned pa[4];
                pa[0] = bf2pack(s[2*kk][0],     s[2*kk][1]);
                pa[1] = bf2pack(s[2*kk][2],     s[2*kk][3]);
                pa[2] = bf2pack(s[2*kk + 1][0], s[2*kk + 1][1]);
                pa[3] = bf2pack(s[2*kk + 1][2], s[2*kk + 1][3]);
                #pragma unroll
                for (int ne = 0; ne < 8; ne++) {
                    int row = kk*16 + (g & 1)*8 + l7;
                    int col = ne*16 + (g >> 1)*8;
                    unsigned r[4];
                    ldsm4t(r, vBase + (row*FQP + col)*2);
                    mma16(O[2*ne],     pa, r);
                    mma16(O[2*ne + 1], pa, r + 2);
                }
            }
        }
    }

    const float inv0 = 1.f / l0, inv1 = 1.f / l1;
    __nv_bfloat16* Cg = ctx + ((size_t)(b * LL + qr0)) * HE + h * EE;
    #pragma unroll
    for (int n = 0; n < 16; n++) {
        const int c = n * 8 + lt * 2;
        *(unsigned*)(Cg + (size_t)lg       * HE + c) = bf2pack(O[n][0]*inv0, O[n][1]*inv0);
        *(unsigned*)(Cg + (size_t)(lg + 8) * HE + c) = bf2pack(O[n][2]*inv1, O[n][3]*inv1);
    }
}

// ============================================================
// Epilogue: out = LayerNorm(x + gelu_erf(ypre)) * gamma + beta
// ============================================================
__global__ __launch_bounds__(256)
void epilogue_ln(const float* __restrict__ x, const float* __restrict__ ypre,
                 const float* __restrict__ gamma, const float* __restrict__ beta,
                 float* __restrict__ out)
{
    const int row = blockIdx.x;
    const int tid = threadIdx.x;
    const float4* xr4 = (const float4*)(x    + (size_t)row*DD);
    const float4* yr4 = (const float4*)(ypre + (size_t)row*DD);
    float4* out4      = (float4*)(out + (size_t)row*DD);

    float4 vals[2];
    float s = 0.f, s2 = 0.f;
    #pragma unroll
    for (int k = 0; k < 2; ++k) {
        const int c = tid + k*256;
        float4 v = yr4[c];
        float4 xv = xr4[c];
        float4 r;
        r.x = xv.x + 0.5f*v.x*(1.f + erff(v.x*0.70710678118654752f));
        r.y = xv.y + 0.5f*v.y*(1.f + erff(v.y*0.70710678118654752f));
        r.z = xv.z + 0.5f*v.z*(1.f + erff(v.z*0.70710678118654752f));
        r.w = xv.w + 0.5f*v.w*(1.f + erff(v.w*0.70710678118654752f));
        vals[k] = r;
        s  += r.x + r.y + r.z + r.w;
        s2 += r.x*r.x + r.y*r.y + r.z*r.z + r.w*r.w;
    }

    __shared__ float red[2][8];
    #pragma unroll
    for (int off = 16; off > 0; off >>= 1) {
        s  += __shfl_down_sync(0xFFFFFFFFu, s,  off);
        s2 += __shfl_down_sync(0xFFFFFFFFu, s2, off);
    }
    if ((tid & 31) == 0) { red[0][tid>>5] = s; red[1][tid>>5] = s2; }
    __syncthreads();
    float ts = 0.f, ts2 = 0.f;
    #pragma unroll
    for (int w = 0; w < 8; w++) { ts += red[0][w]; ts2 += red[1][w]; }

    const float mean = ts * (1.f/2048.f);
    const float var  = ts2 * (1.f/2048.f) - mean*mean;
    const float inv  = rsqrtf(var + 1e-5f);

    const float4* g4 = (const float4*)gamma;
    const float4* b4 = (const float4*)beta;
    #pragma unroll
    for (int k = 0; k < 2; ++k) {
        const int c = tid + k*256;
        float4 gv = g4[c], bv = b4[c], r = vals[k], o;
        o.x = (r.x - mean)*inv*gv.x + bv.x;
        o.y = (r.y - mean)*inv*gv.y + bv.y;
        o.z = (r.z - mean)*inv*gv.z + bv.z;
        o.w = (r.w - mean)*inv*gv.w + bv.w;
        out4[c] = o;
    }
}

// ============================================================
// Launch
// ============================================================
extern "C" void kernel_launch(void* const* d_in, const int* in_sizes, int n_in,
                              void* d_out, int out_size)
{
    const float* x     = (const float*)d_in[0];
    const float* Wq    = (const float*)d_in[1];
    const float* bq    = (const float*)d_in[2];
    const float* Wk    = (const float*)d_in[3];
    const float* bk    = (const float*)d_in[4];
    const float* Wv    = (const float*)d_in[5];
    const float* bv    = (const float*)d_in[6];
    const float* Wo    = (const float*)d_in[7];
    const float* bo    = (const float*)d_in[8];
    const float* gamma = (const float*)d_in[9];
    const float* beta  = (const float*)d_in[10];
    float* out = (float*)d_out;

    __nv_bfloat16 *xb, *Wqkvt, *Wot, *QKV, *CTXb;
    float *bqkv, *Y;
    cudaGetSymbolAddress((void**)&xb,    g_xb);
    cudaGetSymbolAddress((void**)&Wqkvt, g_Wqkvt);
    cudaGetSymbolAddress((void**)&Wot,   g_Wot);
    cudaGetSymbolAddress((void**)&bqkv,  g_bqkv);
    cudaGetSymbolAddress((void**)&QKV,   g_QKV);
    cudaGetSymbolAddress((void**)&CTXb,  g_CTXb);
    cudaGetSymbolAddress((void**)&Y,     g_Y);

    // ---- fused operand prep (single launch) ----
    prep_all<<<PREP_BLOCKS, 256>>>(x, Wq, Wk, Wv, Wo, bq, bk, bv,
                                   xb, Wqkvt, Wot, bqkv);

    // ---- fused QKV projection (128x128 tiles, 256 threads, 4-stage) ----
    cudaFuncSetAttribute(gemm_bf16<true>,  cudaFuncAttributeMaxDynamicSharedMemorySize, GEMM_SMEM);
    cudaFuncSetAttribute(gemm_bf16<false>, cudaFuncAttributeMaxDynamicSharedMemorySize, GEMM_SMEM);
    gemm_bf16<true><<<dim3(QKVN/128, ML/128), 256, GEMM_SMEM>>>(xb, Wqkvt, bqkv, QKV,
                                                                ML, QKVN, DD, QKVN);

    // ---- causal GQA flash attention ----
    cudaFuncSetAttribute(flash_bf16, cudaFuncAttributeMaxDynamicSharedMemorySize, FL_SMEM_BYTES);
    flash_bf16<<<dim3(LL/128, BB*HH), 256, FL_SMEM_BYTES>>>(QKV, CTXb);

    // ---- output projection (fp32 out) ----
    gemm_bf16<false><<<dim3(DD/128, ML/128), 256, GEMM_SMEM>>>(CTXb, Wot, bo, Y,
                                                               ML, DD, HE, DD);

    // ---- GELU + residual + LayerNorm ----
    epilogue_ln<<<ML, 256>>>(x, Y, gamma, beta, out);
}

// round 14
// speedup vs baseline: 1.2488x; 1.0556x over previous
#include <cuda_runtime.h>
#include <cuda_bf16.h>
#include <math.h>
#include <stdint.h>

// Problem constants
#define BB   2
#define LL   2048
#define DD   2048
#define HH   16
#define KVH  4
#define EE   128
#define ML   (BB*LL)        // 4096 rows total
#define HE   (HH*EE)        // 2048
#define KVE  (KVH*EE)       // 512
#define QKVN 3072           // fused Q|K|V projection width

// -------- scratch (device globals; no allocation allowed) --------
__device__ __nv_bfloat16 g_xb[ML*DD];         // x in bf16
__device__ __nv_bfloat16 g_Wqkvt[QKVN*DD];    // [Wq|Wk|Wv]^T [N=3072][K=2048] bf16
__device__ __nv_bfloat16 g_Wot[DD*HE];        // Wo^T [N=2048][K=2048] bf16
__device__ float         g_bqkv[QKVN];        // bq|bk|bv
__device__ __nv_bfloat16 g_QKV[ML*QKVN];      // fused QKV output, row stride 3072
__device__ __nv_bfloat16 g_CTXb[ML*HE];       // attention output bf16
__device__ float         g_Y[ML*DD];          // pre-GELU O-proj output fp32

// ---------------- helpers ----------------
__device__ __forceinline__ void mma16(float* d, const unsigned* a, const unsigned* b) {
    asm volatile(
        "mma.sync.aligned.m16n8k16.row.col.f32.bf16.bf16.f32 "
        "{%0,%1,%2,%3}, {%4,%5,%6,%7}, {%8,%9}, {%0,%1,%2,%3};\n"
        : "+f"(d[0]), "+f"(d[1]), "+f"(d[2]), "+f"(d[3])
        : "r"(a[0]), "r"(a[1]), "r"(a[2]), "r"(a[3]),
          "r"(b[0]), "r"(b[1]));
}

__device__ __forceinline__ void ldsm4(unsigned* r, unsigned addr) {
    asm volatile("ldmatrix.sync.aligned.m8n8.x4.shared.b16 {%0,%1,%2,%3}, [%4];"
                 : "=r"(r[0]), "=r"(r[1]), "=r"(r[2]), "=r"(r[3]) : "r"(addr));
}

__device__ __forceinline__ void ldsm4t(unsigned* r, unsigned addr) {
    asm volatile("ldmatrix.sync.aligned.m8n8.x4.trans.shared.b16 {%0,%1,%2,%3}, [%4];"
                 : "=r"(r[0]), "=r"(r[1]), "=r"(r[2]), "=r"(r[3]) : "r"(addr));
}

__device__ __forceinline__ void cp16(unsigned smem_dst, const void* gmem_src) {
    asm volatile("cp.async.cg.shared.global [%0], [%1], 16;\n" :: "r"(smem_dst), "l"(gmem_src));
}

__device__ __forceinline__ unsigned bf2pack(float x, float y) {
    __nv_bfloat162 v = __float22bfloat162_rn(make_float2(x, y));
    return *(unsigned*)&v;
}

__device__ __forceinline__ unsigned smem_u32(const void* p) {
    unsigned a;
    asm("{ .reg .u64 t; cvta.to.shared.u64 t, %1; cvt.u32.u64 %0, t; }" : "=r"(a) : "l"(p));
    return a;
}

// ============================================================
// Fused prep kernel (single launch)
// ============================================================
#define PREP_BLOCKS 18444

__device__ __forceinline__ void transp_tile(float (*t)[33],
                                            const float* __restrict__ W,
                                            __nv_bfloat16* __restrict__ Wt,
                                            int Kd, int Nd, int bx, int by, int tid)
{
    const int n0 = bx * 32, k0 = by * 32;
    const int tx = tid & 31, ty = tid >> 5;
    #pragma unroll
    for (int i = 0; i < 4; i++)
        t[ty + 8*i][tx] = W[(size_t)(k0 + ty + 8*i) * Nd + n0 + tx];
    __syncthreads();
    #pragma unroll
    for (int i = 0; i < 4; i++)
        Wt[(size_t)(n0 + ty + 8*i) * Kd + k0 + tx] = __float2bfloat16(t[tx][ty + 8*i]);
}

__global__ __launch_bounds__(256)
void prep_all(const float* __restrict__ x,
              const float* __restrict__ Wq, const float* __restrict__ Wk,
              const float* __restrict__ Wv, const float* __restrict__ Wo,
              const float* __restrict__ bq, const float* __restrict__ bk,
              const float* __restrict__ bv,
              __nv_bfloat16* __restrict__ xb, __nv_bfloat16* __restrict__ Wqkvt,
              __nv_bfloat16* __restrict__ Wot, float* __restrict__ bqkv)
{
    __shared__ float t[32][33];
    const int bid = blockIdx.x;
    const int tid = threadIdx.x;

    if (bid < 8192) {
        int i = bid * 256 + tid;
        float4 v = ((const float4*)x)[i];
        uint2 o;
        o.x = bf2pack(v.x, v.y);
        o.y = bf2pack(v.z, v.w);
        ((uint2*)xb)[i] = o;
    } else if (bid < 12288) {
        int tt = bid - 8192;
        transp_tile(t, Wq, Wqkvt, DD, HE, tt & 63, tt >> 6, tid);
    } else if (bid < 13312) {
        int tt = bid - 12288;
        transp_tile(t, Wk, Wqkvt + (size_t)2048*DD, DD, KVE, tt & 15, tt >> 4, tid);
    } else if (bid < 14336) {
        int tt = bid - 13312;
        transp_tile(t, Wv, Wqkvt + (size_t)2560*DD, DD, KVE, tt & 15, tt >> 4, tid);
    } else if (bid < 18432) {
        int tt = bid - 14336;
        transp_tile(t, Wo, Wot, HE, DD, tt & 63, tt >> 6, tid);
    } else {
        int i = (bid - 18432) * 256 + tid;
        if (i < 2048)        bqkv[i] = bq[i];
        else if (i < 2560)   bqkv[i] = bk[i - 2048];
        else if (i < 3072)   bqkv[i] = bv[i - 2560];
    }
}

// ============================================================
// bf16 tensor-core GEMM: mma.sync + ldmatrix, 4-stage cp.async pipeline
// AND register-level fragment double buffering.
// CTA tile 128x128, BK=32, 256 threads = 8 warps (64x32 warp tile, 2x4).
// ============================================================
#define GBK    32
#define GPAD   40                        // halves/row (80B, LDSM conflict-free)
#define T_ST   (128*GPAD*2)              // 10240 B per matrix per stage
#define GSTG   4
#define GEMM_SMEM (GSTG*2*T_ST)          // 81920 B -> 2 CTAs/SM

template<bool OUT_BF16>
__global__ __launch_bounds__(256, 2)
void gemm_bf16(const __nv_bfloat16* __restrict__ A, const __nv_bfloat16* __restrict__ Bt,
               const float* __restrict__ bias, void* __restrict__ Cout,
               int M, int N, int K, int ldc)
{
    extern __shared__ __nv_bfloat16 gsm[];
    const unsigned AsU = smem_u32(gsm);
    const unsigned BsU = AsU + GSTG * T_ST;

    const int tid  = threadIdx.x;
    const int w    = tid >> 5, lane = tid & 31;
    const int lt   = lane & 3;
    const int l7   = lane & 7, g = lane >> 3;
    const int wm   = w & 1, wn = w >> 1;        // 2x4 warp grid
    const int bx   = blockIdx.x, by = blockIdx.y;

    const __nv_bfloat16* Ag = A  + (size_t)(by * 128) * K;
    const __nv_bfloat16* Bg = Bt + (size_t)(bx * 128) * K;

    float acc[4][4][4];
    #pragma unroll
    for (int mt = 0; mt < 4; mt++)
        #pragma unroll
        for (int nt = 0; nt < 4; nt++)
            #pragma unroll
            for (int f = 0; f < 4; f++) acc[mt][nt][f] = 0.f;

    const int KT = K / GBK;

    auto issue = [&](int kt) {
        if (kt < KT) {
            const int buf = kt & (GSTG - 1);
            const int k0 = kt * GBK;
            #pragma unroll
            for (int i = 0; i < 2; i++) {      // A: 512 chunks
                int q = tid + i * 256;
                int r = q >> 2, c8 = (q & 3) * 8;
                cp16(AsU + buf*T_ST + (r*GPAD + c8)*2, Ag + (size_t)r * K + k0 + c8);
            }
            #pragma unroll
            for (int i = 0; i < 2; i++) {      // B: 512 chunks
                int q = tid + i * 256;
                int r = q >> 2, c8 = (q & 3) * 8;
                cp16(BsU + buf*T_ST + (r*GPAD + c8)*2, Bg + (size_t)r * K + k0 + c8);
            }
        }
        asm volatile("cp.async.commit_group;\n");   // empty group past the end
    };

    const int arow = wm*64 + (g & 1)*8 + l7;
    const int acol = (g >> 1)*8;
    const int brow0 = wn*32 + (g >> 1)*8 + l7;
    const int brow1 = wn*32 + 16 + (g >> 1)*8 + l7;
    const int bcol = (g & 1)*8;

    auto load_frags = [&](unsigned aBase, unsigned bBase, int k8,
                          unsigned (&af)[4][4], unsigned (&bf)[4][2]) {
        #pragma unroll
        for (int mt = 0; mt < 4; mt++)
            ldsm4(af[mt], aBase + ((arow + mt*16)*GPAD + k8 + acol)*2);
        unsigned r0[4], r1[4];
        ldsm4(r0, bBase + (brow0*GPAD + k8 + bcol)*2);
        ldsm4(r1, bBase + (brow1*GPAD + k8 + bcol)*2);
        bf[0][0] = r0[0]; bf[0][1] = r0[1];
        bf[1][0] = r0[2]; bf[1][1] = r0[3];
        bf[2][0] = r1[0]; bf[2][1] = r1[1];
        bf[3][0] = r1[2]; bf[3][1] = r1[3];
    };

    auto mma_block = [&](const unsigned (&af)[4][4], const unsigned (&bf)[4][2]) {
        #pragma unroll
        for (int mt = 0; mt < 4; mt++)
            #pragma unroll
            for (int nt = 0; nt < 4; nt++)
                mma16(acc[mt][nt], af[mt], bf[nt]);
    };

    issue(0); issue(1); issue(2);
    asm volatile("cp.async.wait_group 2;\n");
    __syncthreads();

    unsigned afA[4][4], bfA[4][2];
    unsigned afB[4][4], bfB[4][2];
    load_frags(AsU, BsU, 0, afA, bfA);

    for (int kt = 0; kt < KT; ++kt) {
        const int buf = kt & (GSTG - 1);
        const unsigned aBase = AsU + buf*T_ST;
        const unsigned bBase = BsU + buf*T_ST;

        load_frags(aBase, bBase, 16, afB, bfB);
        mma_block(afA, bfA);

        issue(kt + 3);
        asm volatile("cp.async.wait_group 2;\n");
        __syncthreads();

        const int nbuf = (kt + 1) & (GSTG - 1);
        load_frags(AsU + nbuf*T_ST, BsU + nbuf*T_ST, 0, afA, bfA);
        mma_block(afB, bfB);
    }

    const int lg = lane >> 2;
    #pragma unroll
    for (int mt = 0; mt < 4; mt++) {
        const int r0 = by * 128 + wm * 64 + mt * 16 + lg;
        #pragma unroll
        for (int nt = 0; nt < 4; nt++) {
            const int c = bx * 128 + wn * 32 + nt * 8 + lt * 2;
            const float b0 = bias[c], b1 = bias[c + 1];
            if (OUT_BF16) {
                __nv_bfloat16* Cb = (__nv_bfloat16*)Cout;
                *(unsigned*)(Cb + (size_t)r0       * ldc + c) =
                    bf2pack(acc[mt][nt][0] + b0, acc[mt][nt][1] + b1);
                *(unsigned*)(Cb + (size_t)(r0 + 8) * ldc + c) =
                    bf2pack(acc[mt][nt][2] + b0, acc[mt][nt][3] + b1);
            } else {
                float* Cf = (float*)Cout;
                float2 o0, o1;
                o0.x = acc[mt][nt][0] + b0;  o0.y = acc[mt][nt][1] + b1;
                o1.x = acc[mt][nt][2] + b0;  o1.y = acc[mt][nt][3] + b1;
                *(float2*)(Cf + (size_t)r0       * ldc + c) = o0;
                *(float2*)(Cf + (size_t)(r0 + 8) * ldc + c) = o1;
            }
        }
    }
}

// ============================================================
// Flash attention (causal, GQA), bf16 mma.sync + ldmatrix.
// Bc=128: halves per-tile fixed costs (barriers, shuffle reductions,
// O-rescales) vs Bc=64. Q frags register-resident; V via ldmatrix.trans;
// P converted C-frag -> A-frag in registers; K/V cp.async double-buffered.
// Block: 128 q-rows, 8 warps x 16 rows, E=128. 1 CTA/SM (174KB smem).
// ============================================================
#define FQP 136   // row pad in halves (272B, LDSM conflict-free)
#define FTILE_B (128*FQP*2)                       // 34816 B per K or V tile
#define FL_SMEM_BYTES (FTILE_B + 4*FTILE_B)       // Q + K0,K1,V0,V1 = 174080

__global__ __launch_bounds__(256)
void flash_bf16(const __nv_bfloat16* __restrict__ QKV, __nv_bfloat16* __restrict__ ctx)
{
    extern __shared__ __nv_bfloat16 sm[];
    const unsigned QsU = smem_u32(sm);
    const unsigned KsU = QsU + FTILE_B;
    const unsigned VsU = KsU + 2 * FTILE_B;

    const int tid  = threadIdx.x;
    const int w    = tid >> 5, lane = tid & 31;
    const int lg   = lane >> 2, lt = lane & 3;
    const int l7   = lane & 7, g = lane >> 3;
    const int h2   = w >> 2, wq = w & 3;
    const int bh   = blockIdx.y;
    const int b    = bh / HH, h = bh % HH, kvh = h % KVH;
    const int bxr  = (int)gridDim.x - 1 - (int)blockIdx.x;   // longest first
    const int qb   = bxr * 128;
    const int qrl  = h2 * 64 + wq * 16;
    const int qr0  = qb + qrl;
    const float scale = 0.08838834764831845f;

    const __nv_bfloat16* Kg0 = QKV + (size_t)(b * LL) * QKVN + 2048 + kvh * EE;

    auto issue = [&](int buf, int kb) {
        const __nv_bfloat16* Kg = Kg0 + (size_t)kb * QKVN;
        const __nv_bfloat16* Vg = Kg + KVE;
        #pragma unroll
        for (int i = 0; i < 8; i++) {          // 128 rows x 16 chunks each
            int q = tid + i * 256;
            int r = q >> 4, c8 = (q & 15) * 8;
            cp16(KsU + buf*FTILE_B + (r*FQP + c8)*2, Kg + (size_t)r * QKVN + c8);
            cp16(VsU + buf*FTILE_B + (r*FQP + c8)*2, Vg + (size_t)r * QKVN + c8);
        }
        asm volatile("cp.async.commit_group;\n");
    };

    issue(0, 0);
    {
        const __nv_bfloat16* Qg = QKV + ((size_t)(b * LL + qb)) * QKVN + h * EE;
        #pragma unroll
        for (int i = 0; i < 8; i++) {
            int q = tid + i * 256;
            int r = q >> 4, c8 = (q & 15) * 8;
            *(uint4*)(sm + r * FQP + c8) = *(const uint4*)(Qg + (size_t)r * QKVN + c8);
        }
    }
    __syncthreads();

    unsigned qf[8][4];
    #pragma unroll
    for (int e8 = 0; e8 < 8; e8++) {
        int row = qrl + (g & 1)*8 + l7;
        int col = e8*16 + (g >> 1)*8;
        ldsm4(qf[e8], QsU + (row*FQP + col)*2);
    }

    float O[16][4];
    #pragma unroll
    for (int n = 0; n < 16; n++)
        #pragma unroll
        for (int f = 0; f < 4; f++) O[n][f] = 0.f;
    float m0 = -INFINITY, m1 = -INFINITY, l0 = 0.f, l1 = 0.f;

    const int ntiles = bxr + 1;
    for (int t = 0; t < ntiles; ++t) {
        const int kb = t * 128;
        asm volatile("cp.async.wait_group 0;\n");
        __syncthreads();
        if (t + 1 < ntiles) issue((t + 1) & 1, kb + 128);
        const int buf = t & 1;
        const unsigned kBase = KsU + buf*FTILE_B;
        const unsigned vBase = VsU + buf*FTILE_B;

        // ---- S = Q @ K^T (16 x 128 per warp) ----
        float s[16][4];
        #pragma unroll
        for (int nn = 0; nn < 16; nn++)
            #pragma unroll
            for (int f = 0; f < 4; f++) s[nn][f] = 0.f;

        #pragma unroll
        for (int e8 = 0; e8 < 8; e8++) {
            #pragma unroll
            for (int np = 0; np < 8; np++) {
                int row = np*16 + (g >> 1)*8 + l7;
                int col = e8*16 + (g & 1)*8;
                unsigned r[4];
                ldsm4(r, kBase + (row*FQP + col)*2);
                mma16(s[2*np],     qf[e8], r);
                mma16(s[2*np + 1], qf[e8], r + 2);
            }
        }
        #pragma unroll
        for (int nn = 0; nn < 16; nn++)
            #pragma unroll
            for (int f = 0; f < 4; f++) s[nn][f] *= scale;

        // ---- causal mask (diagonal tile only: kb == qb) ----
        if (kb + 127 > qr0) {
            const int r0g = qr0 + lg, r1g = qr0 + lg + 8;
            #pragma unroll
            for (int nn = 0; nn < 16; nn++) {
                const int c0 = kb + nn * 8 + lt * 2;
                if (c0     > r0g) s[nn][0] = -1e30f;
                if (c0 + 1 > r0g) s[nn][1] = -1e30f;
                if (c0     > r1g) s[nn][2] = -1e30f;
                if (c0 + 1 > r1g) s[nn][3] = -1e30f;
            }
        }

        // ---- online softmax (rows lg, lg+8) ----
        float mx0 = -1e30f, mx1 = -1e30f;
        #pragma unroll
        for (int nn = 0; nn < 16; nn++) {
            mx0 = fmaxf(mx0, fmaxf(s[nn][0], s[nn][1]));
            mx1 = fmaxf(mx1, fmaxf(s[nn][2], s[nn][3]));
        }
        mx0 = fmaxf(mx0, __shfl_xor_sync(0xFFFFFFFFu, mx0, 1));
        mx0 = fmaxf(mx0, __shfl_xor_sync(0xFFFFFFFFu, mx0, 2));
        mx1 = fmaxf(mx1, __shfl_xor_sync(0xFFFFFFFFu, mx1, 1));
        mx1 = fmaxf(mx1, __shfl_xor_sync(0xFFFFFFFFu, mx1, 2));

        const float mn0 = fmaxf(m0, mx0), mn1 = fmaxf(m1, mx1);
        const float a0 = __expf(m0 - mn0), a1 = __expf(m1 - mn1);
        float rs0 = 0.f, rs1 = 0.f;
        #pragma unroll
        for (int nn = 0; nn < 16; nn++) {
            float p0 = __expf(s[nn][0] - mn0);
            float p1 = __expf(s[nn][1] - mn0);
            float p2 = __expf(s[nn][2] - mn1);
            float p3 = __expf(s[nn][3] - mn1);
            s[nn][0] = p0; s[nn][1] = p1; s[nn][2] = p2; s[nn][3] = p3;
            rs0 += p0 + p1; rs1 += p2 + p3;
        }
        rs0 += __shfl_xor_sync(0xFFFFFFFFu, rs0, 1);
        rs0 += __shfl_xor_sync(0xFFFFFFFFu, rs0, 2);
        rs1 += __shfl_xor_sync(0xFFFFFFFFu, rs1, 1);
        rs1 += __shfl_xor_sync(0xFFFFFFFFu, rs1, 2);

        m0 = mn0; m1 = mn1;
        l0 = l0 * a0 + rs0;
        l1 = l1 * a1 + rs1;

        #pragma unroll
        for (int n = 0; n < 16; n++) {
            O[n][0] *= a0; O[n][1] *= a0;
            O[n][2] *= a1; O[n][3] *= a1;
        }

        // ---- O += P @ V : P converted C-frag -> A-frag in registers ----
        #pragma unroll
        for (int kk = 0; kk < 8; kk++) {
            unsigned pa[4];
            pa[0] = bf2pack(s[2*kk][0],     s[2*kk][1]);
            pa[1] = bf2pack(s[2*kk][2],     s[2*kk][3]);
            pa[2] = bf2pack(s[2*kk + 1][0], s[2*kk + 1][1]);
            pa[3] = bf2pack(s[2*kk + 1][2], s[2*kk + 1][3]);
            #pragma unroll
            for (int ne = 0; ne < 8; ne++) {
                int row = kk*16 + (g & 1)*8 + l7;
                int col = ne*16 + (g >> 1)*8;
                unsigned r[4];
                ldsm4t(r, vBase + (row*FQP + col)*2);
                mma16(O[2*ne],     pa, r);
                mma16(O[2*ne + 1], pa, r + 2);
            }
        }
    }

    const float inv0 = 1.f / l0, inv1 = 1.f / l1;
    __nv_bfloat16* Cg = ctx + ((size_t)(b * LL + qr0)) * HE + h * EE;
    #pragma unroll
    for (int n = 0; n < 16; n++) {
        const int c = n * 8 + lt * 2;
        *(unsigned*)(Cg + (size_t)lg       * HE + c) = bf2pack(O[n][0]*inv0, O[n][1]*inv0);
        *(unsigned*)(Cg + (size_t)(lg + 8) * HE + c) = bf2pack(O[n][2]*inv1, O[n][3]*inv1);
    }
}

// ============================================================
// Epilogue: out = LayerNorm(x + gelu_erf(ypre)) * gamma + beta
// ============================================================
__global__ __launch_bounds__(256)
void epilogue_ln(const float* __restrict__ x, const float* __restrict__ ypre,
                 const float* __restrict__ gamma, const float* __restrict__ beta,
                 float* __restrict__ out)
{
    const int row = blockIdx.x;
    const int tid = threadIdx.x;
    const float4* xr4 = (const float4*)(x    + (size_t)row*DD);
    const float4* yr4 = (const float4*)(ypre + (size_t)row*DD);
    float4* out4      = (float4*)(out + (size_t)row*DD);

    float4 vals[2];
    float s = 0.f, s2 = 0.f;
    #pragma unroll
    for (int k = 0; k < 2; ++k) {
        const int c = tid + k*256;
        float4 v = yr4[c];
        float4 xv = xr4[c];
        float4 r;
        r.x = xv.x + 0.5f*v.x*(1.f + erff(v.x*0.70710678118654752f));
        r.y = xv.y + 0.5f*v.y*(1.f + erff(v.y*0.70710678118654752f));
        r.z = xv.z + 0.5f*v.z*(1.f + erff(v.z*0.70710678118654752f));
        r.w = xv.w + 0.5f*v.w*(1.f + erff(v.w*0.70710678118654752f));
        vals[k] = r;
        s  += r.x + r.y + r.z + r.w;
        s2 += r.x*r.x + r.y*r.y + r.z*r.z + r.w*r.w;
    }

    __shared__ float red[2][8];
    #pragma unroll
    for (int off = 16; off > 0; off >>= 1) {
        s  += __shfl_down_sync(0xFFFFFFFFu, s,  off);
        s2 += __shfl_down_sync(0xFFFFFFFFu, s2, off);
    }
    if ((tid & 31) == 0) { red[0][tid>>5] = s; red[1][tid>>5] = s2; }
    __syncthreads();
    float ts = 0.f, ts2 = 0.f;
    #pragma unroll
    for (int w = 0; w < 8; w++) { ts += red[0][w]; ts2 += red[1][w]; }

    const float mean = ts * (1.f/2048.f);
    const float var  = ts2 * (1.f/2048.f) - mean*mean;
    const float inv  = rsqrtf(var + 1e-5f);

    const float4* g4 = (const float4*)gamma;
    const float4* b4 = (const float4*)beta;
    #pragma unroll
    for (int k = 0; k < 2; ++k) {
        const int c = tid + k*256;
        float4 gv = g4[c], bv = b4[c], r = vals[k], o;
        o.x = (r.x - mean)*inv*gv.x + bv.x;
        o.y = (r.y - mean)*inv*gv.y + bv.y;
        o.z = (r.z - mean)*inv*gv.z + bv.z;
        o.w = (r.w - mean)*inv*gv.w + bv.w;
        out4[c] = o;
    }
}

// ============================================================
// Launch
// ============================================================
extern "C" void kernel_launch(void* const* d_in, const int* in_sizes, int n_in,
                              void* d_out, int out_size)
{
    const float* x     = (const float*)d_in[0];
    const float* Wq    = (const float*)d_in[1];
    const float* bq    = (const float*)d_in[2];
    const float* Wk    = (const float*)d_in[3];
    const float* bk    = (const float*)d_in[4];
    const float* Wv    = (const float*)d_in[5];
    const float* bv    = (const float*)d_in[6];
    const float* Wo    = (const float*)d_in[7];
    const float* bo    = (const float*)d_in[8];
    const float* gamma = (const float*)d_in[9];
    const float* beta  = (const float*)d_in[10];
    float* out = (float*)d_out;

    __nv_bfloat16 *xb, *Wqkvt, *Wot, *QKV, *CTXb;
    float *bqkv, *Y;
    cudaGetSymbolAddress((void**)&xb,    g_xb);
    cudaGetSymbolAddress((void**)&Wqkvt, g_Wqkvt);
    cudaGetSymbolAddress((void**)&Wot,   g_Wot);
    cudaGetSymbolAddress((void**)&bqkv,  g_bqkv);
    cudaGetSymbolAddress((void**)&QKV,   g_QKV);
    cudaGetSymbolAddress((void**)&CTXb,  g_CTXb);
    cudaGetSymbolAddress((void**)&Y,     g_Y);

    // ---- fused operand prep (single launch) ----
    prep_all<<<PREP_BLOCKS, 256>>>(x, Wq, Wk, Wv, Wo, bq, bk, bv,
                                   xb, Wqkvt, Wot, bqkv);

    // ---- fused QKV projection ----
    cudaFuncSetAttribute(gemm_bf16<true>,  cudaFuncAttributeMaxDynamicSharedMemorySize, GEMM_SMEM);
    cudaFuncSetAttribute(gemm_bf16<false>, cudaFuncAttributeMaxDynamicSharedMemorySize, GEMM_SMEM);
    gemm_bf16<true><<<dim3(QKVN/128, ML/128), 256, GEMM_SMEM>>>(xb, Wqkvt, bqkv, QKV,
                                                                ML, QKVN, DD, QKVN);

    // ---- causal GQA flash attention (Bc=128) ----
    cudaFuncSetAttribute(flash_bf16, cudaFuncAttributeMaxDynamicSharedMemorySize, FL_SMEM_BYTES);
    flash_bf16<<<dim3(LL/128, BB*HH), 256, FL_SMEM_BYTES>>>(QKV, CTXb);

    // ---- output projection (fp32 out) ----
    gemm_bf16<false><<<dim3(DD/128, ML/128), 256, GEMM_SMEM>>>(CTXb, Wot, bo, Y,
                                                               ML, DD, HE, DD);

    // ---- GELU + residual + LayerNorm ----
    epilogue_ln<<<ML, 256>>>(x, Y, gamma, beta, out);
}